// round 13
// baseline (speedup 1.0000x reference)
#include <cuda_runtime.h>
#include <cuda_bf16.h>
#include <cuda_fp16.h>
#include <cstdint>
#include <math.h>

#define BB 64
#define NN 64
#define DD 2048
#define NBW 8
#define WW 57
#define MPAD2 3712
#define SCALE 0.02209708691207961f
#define LNEPS 1e-5f
#define NW ((size_t)DD * DD)

// ============ scratch ============
__device__ float g_P  [BB * NN * DD];
__device__ float g_Vn [BB * NN * DD];
__device__ float g_h  [BB * WW * DD];
__device__ float g_P2 [MPAD2 * DD];
__device__ float g_c  [BB * WW * NBW];
__device__ float g_S  [BB];
__device__ float g_dot2[4 * BB * 64 * 64];
__device__ float g_u  [2 * DD];
__device__ float g_upart[2 * 16 * DD];
__device__ float g_part[8 * 128 * DD];

__device__ __align__(16) __half        g_fc16 [BB * NN * DD];
__device__ __align__(16) __half        g_wT16 [4 * NW];   // WqT, WkT, Wq2T, Wk2T
__device__ __align__(16) __half        g_wv16 [NW];       // Wv (stage 1, fp16)
__device__ __align__(16) __nv_bfloat16 g_wv2_hi[NW];      // Wv2 (final, bf16 hi/lo)
__device__ __align__(16) __nv_bfloat16 g_wv2_lo[NW];
__device__ __align__(16) __half        g_G16  [2 * NW];   // Gram matrices
__device__ __align__(16) __nv_bfloat16 g_hn_hi[MPAD2 * DD];  // rows >=3648 stay zero
__device__ __align__(16) __nv_bfloat16 g_hn_lo[MPAD2 * DD];
__device__ __align__(16) __half        g_hn16 [MPAD2 * DD];
__device__ __align__(16) __nv_bfloat16 g_hb_hi[128 * DD];    // rows >=64 stay zero
__device__ __align__(16) __nv_bfloat16 g_hb_lo[128 * DD];

// ============ merged splits: fc->fp16, Wv->fp16, Wv2->bf16 hi/lo ============
__global__ void split_all16(const float* __restrict__ fc, const float* __restrict__ wv,
                            const float* __restrict__ wv2)
{
    int i = blockIdx.x * 256 + threadIdx.x;
    const int NFC = BB * NN * DD;
    const int NWI = (int)NW;
    if (i < NFC) {
        g_fc16[i] = __float2half(fc[i]);
    } else if (i < NFC + NWI) {
        int j = i - NFC;
        g_wv16[j] = __float2half(wv[j]);
    } else {
        int j = i - NFC - NWI;
        float v = wv2[j];
        __nv_bfloat16 h = __float2bfloat16(v);
        g_wv2_hi[j] = h;
        g_wv2_lo[j] = __float2bfloat16(v - __bfloat162float(h));
    }
}

// transpose to fp16 with coalesced half2 stores: wT16[z][i][m] = W[m][i]
struct SplitTSrc { const float* W[4]; };
__global__ void splitT_kernel(const __grid_constant__ SplitTSrc s)
{
    const int z = blockIdx.z;
    const float* __restrict__ W = s.W[z];
    __half* __restrict__ o = g_wT16 + (size_t)z * NW;
    __shared__ float t[64][65];
    const int m0 = blockIdx.y * 64, i0 = blockIdx.x * 64;
    const int tx = threadIdx.x, ty = threadIdx.y;  // 32, 8
#pragma unroll
    for (int rr = ty; rr < 64; rr += 8) {
        t[rr][tx]      = W[(size_t)(m0 + rr) * DD + i0 + tx];
        t[rr][tx + 32] = W[(size_t)(m0 + rr) * DD + i0 + tx + 32];
    }
    __syncthreads();
#pragma unroll
    for (int ii = ty; ii < 64; ii += 8) {
        __half2 v = __floats2half2_rn(t[tx * 2][ii], t[tx * 2 + 1][ii]);
        *(__half2*)(o + (size_t)(i0 + ii) * DD + m0 + tx * 2) = v;
    }
}

// ============ u[z][j] = sum_m bq[m] * Wk[m][j] ============
__global__ void u_part(const float* __restrict__ b1, const float* __restrict__ W1,
                       const float* __restrict__ b2, const float* __restrict__ W2)
{
    const int z = blockIdx.z;
    const float* __restrict__ b = z ? b2 : b1;
    const float* __restrict__ W = z ? W2 : W1;
    const int j = blockIdx.x * 256 + threadIdx.x;
    const int m0 = blockIdx.y * 128;
    float a = 0.f;
    for (int m = m0; m < m0 + 128; m++) a += b[m] * W[(size_t)m * DD + j];
    g_upart[((size_t)z * 16 + blockIdx.y) * DD + j] = a;
}
__global__ void u_reduce()
{
    const int z = blockIdx.y;
    const int j = blockIdx.x * 256 + threadIdx.x;
    float a = 0.f;
#pragma unroll
    for (int s = 0; s < 16; s++) a += g_upart[((size_t)z * 16 + s) * DD + j];
    g_u[z * DD + j] = a;
}

// ============ common GEMM plumbing ============
#define PITCH 80
__device__ __forceinline__ void cp16(uint32_t saddr, const void* gaddr) {
    asm volatile("cp.async.cg.shared.global [%0], [%1], 16;" :: "r"(saddr), "l"(gaddr));
}
__device__ __forceinline__ uint32_t smem_u32(const void* p) {
    uint32_t a;
    asm("{ .reg .u64 t; cvta.to.shared.u64 t, %1; cvt.u32.u64 %0, t; }" : "=r"(a) : "l"(p));
    return a;
}
#define MMA_BF16(d, a, b) \
    asm volatile("mma.sync.aligned.m16n8k16.row.col.f32.bf16.bf16.f32 " \
        "{%0,%1,%2,%3},{%4,%5,%6,%7},{%8,%9},{%0,%1,%2,%3};" \
        : "+f"((d)[0]), "+f"((d)[1]), "+f"((d)[2]), "+f"((d)[3]) \
        : "r"((a)[0]), "r"((a)[1]), "r"((a)[2]), "r"((a)[3]), "r"((b)[0]), "r"((b)[1]))
#define MMA_F16(d, a, b) \
    asm volatile("mma.sync.aligned.m16n8k16.row.col.f32.f16.f16.f32 " \
        "{%0,%1,%2,%3},{%4,%5,%6,%7},{%8,%9},{%0,%1,%2,%3};" \
        : "+f"((d)[0]), "+f"((d)[1]), "+f"((d)[2]), "+f"((d)[3]) \
        : "r"((a)[0]), "r"((a)[1]), "r"((a)[2]), "r"((a)[3]), "r"((b)[0]), "r"((b)[1]))
#define LDSM_X4(r, addr) \
    asm volatile("ldmatrix.sync.aligned.m8n8.x4.shared.b16 {%0,%1,%2,%3}, [%4];" \
        : "=r"((r)[0]), "=r"((r)[1]), "=r"((r)[2]), "=r"((r)[3]) : "r"(addr))

__device__ __forceinline__ uint32_t a_lane_off(int lane) {
    return (uint32_t)((lane & 15) * PITCH + ((lane >> 4) & 1) * 16);
}
__device__ __forceinline__ uint32_t b_lane_off(int lane) {
    return (uint32_t)(((lane & 7) + ((lane >> 4) & 1) * 8) * PITCH + ((lane >> 3) & 1) * 16);
}

// ============ 3-product bf16 GEMM (final projection only), k-split ============
#define STAGE_BYTES 40960
#define OFF_AH 0
#define OFF_AL 10240
#define OFF_BH 20480
#define OFF_BL 30720

struct GemmBatch {
    const __nv_bfloat16* Ah;
    const __nv_bfloat16* Al;
    const __nv_bfloat16* Bh;
    const __nv_bfloat16* Bl;
    float* C;
    int kSplit;
};

__global__ void __launch_bounds__(128, 2) gemm_mma_b(const __grid_constant__ GemmBatch p)
{
    extern __shared__ char smem[];
    const uint32_t sb = smem_u32(smem);
    const int tid = threadIdx.x;
    const int wid = tid >> 5, lane = tid & 31;
    const int quad = lane >> 2, four = lane & 3;
    const int rowBase = blockIdx.y * 128, colBase = blockIdx.x * 128;
    const int warpM = (wid >> 1) * 64, warpN = (wid & 1) * 64;
    const int slice = blockIdx.z;
    const int chunksPer = (DD / 32) / p.kSplit;
    const int c0 = slice * chunksPer;

    const __nv_bfloat16* __restrict__ Ahi = p.Ah;
    const __nv_bfloat16* __restrict__ Alo = p.Al;
    const __nv_bfloat16* __restrict__ Bhi = p.Bh;
    const __nv_bfloat16* __restrict__ Blo = p.Bl;

    const uint32_t aoff = a_lane_off(lane) + (uint32_t)warpM * PITCH;
    const uint32_t boff = b_lane_off(lane) + (uint32_t)warpN * PITCH;

    float acc[4][8][4];
#pragma unroll
    for (int mi = 0; mi < 4; mi++)
#pragma unroll
        for (int ni = 0; ni < 8; ni++)
#pragma unroll
            for (int r = 0; r < 4; r++) acc[mi][ni][r] = 0.f;

    auto load_stage = [&](int s, int k0) {
        const uint32_t base = sb + (uint32_t)s * STAGE_BYTES;
#pragma unroll
        for (int pp = 0; pp < 4; pp++) {
            int c = tid + pp * 128;
            int row = c >> 2, col = c & 3;
            uint32_t soff = row * PITCH + col * 16;
            size_t ga = (size_t)(rowBase + row) * DD + k0 + col * 8;
            size_t gb = (size_t)(colBase + row) * DD + k0 + col * 8;
            cp16(base + OFF_AH + soff, Ahi + ga);
            cp16(base + OFF_AL + soff, Alo + ga);
            cp16(base + OFF_BH + soff, Bhi + gb);
            cp16(base + OFF_BL + soff, Blo + gb);
        }
        asm volatile("cp.async.commit_group;");
    };

    load_stage(0, c0 * 32);

    for (int cc = 0; cc < chunksPer; cc++) {
        if (cc + 1 < chunksPer) {
            load_stage((cc + 1) & 1, (c0 + cc + 1) * 32);
            asm volatile("cp.async.wait_group 1;");
        } else {
            asm volatile("cp.async.wait_group 0;");
        }
        __syncthreads();

        const uint32_t stg = sb + (uint32_t)(cc & 1) * STAGE_BYTES;
#pragma unroll
        for (int kk = 0; kk < 2; kk++) {
            const uint32_t kb = kk * 32;
            uint32_t ah[4][4], al[4][4], bhq[4][4], blq[4][4];
#pragma unroll
            for (int mi = 0; mi < 4; mi++) {
                uint32_t ad = stg + aoff + (uint32_t)(mi * 16) * PITCH + kb;
                LDSM_X4(ah[mi], ad + OFF_AH);
                LDSM_X4(al[mi], ad + OFF_AL);
            }
#pragma unroll
            for (int np = 0; np < 4; np++) {
                uint32_t bd = stg + boff + (uint32_t)(np * 16) * PITCH + kb;
                LDSM_X4(bhq[np], bd + OFF_BH);
                LDSM_X4(blq[np], bd + OFF_BL);
            }
#pragma unroll
            for (int mi = 0; mi < 4; mi++)
#pragma unroll
                for (int ni = 0; ni < 8; ni++)
                    MMA_BF16(acc[mi][ni], ah[mi], (&bhq[ni >> 1][(ni & 1) * 2]));
#pragma unroll
            for (int mi = 0; mi < 4; mi++)
#pragma unroll
                for (int ni = 0; ni < 8; ni++)
                    MMA_BF16(acc[mi][ni], ah[mi], (&blq[ni >> 1][(ni & 1) * 2]));
#pragma unroll
            for (int mi = 0; mi < 4; mi++)
#pragma unroll
                for (int ni = 0; ni < 8; ni++)
                    MMA_BF16(acc[mi][ni], al[mi], (&bhq[ni >> 1][(ni & 1) * 2]));
        }
        __syncthreads();
    }

    float* __restrict__ Cp = p.C + (size_t)slice * (gridDim.y * 128) * DD;
#pragma unroll
    for (int mi = 0; mi < 4; mi++) {
        int gr0 = rowBase + warpM + mi * 16 + quad;
        int gr1 = gr0 + 8;
#pragma unroll
        for (int ni = 0; ni < 8; ni++) {
            int gc = colBase + warpN + ni * 8 + four * 2;
            *(float2*)&Cp[(size_t)gr0 * DD + gc] = make_float2(acc[mi][ni][0], acc[mi][ni][1]);
            *(float2*)&Cp[(size_t)gr1 * DD + gc] = make_float2(acc[mi][ni][2], acc[mi][ni][3]);
        }
    }
}

// ============ single-product fp16 GEMM, 128 threads, k-chunk 64, 3-stage ============
#define PITCH64 144
#define STAGE64 36864
#define OFF_B64 18432

struct Gemm16Batch {
    const __half* A[2];
    const __half* B[2];
    const float* bias[2];
    float* C[2];
    __half* C16[2];
    int Mstore;
};

__global__ void __launch_bounds__(128, 2) gemm_f16(const __grid_constant__ Gemm16Batch p)
{
    extern __shared__ char smem[];
    const uint32_t sb = smem_u32(smem);
    const int tid = threadIdx.x;
    const int wid = tid >> 5, lane = tid & 31;
    const int quad = lane >> 2, four = lane & 3;
    const int rowBase = blockIdx.y * 128, colBase = blockIdx.x * 128;
    const int warpM = (wid >> 1) * 64, warpN = (wid & 1) * 64;
    const int z = blockIdx.z;

    const __half* __restrict__ A = p.A[z];
    const __half* __restrict__ B = p.B[z];

    const uint32_t aoff = (uint32_t)((lane & 15) * PITCH64 + ((lane >> 4) & 1) * 16)
                        + (uint32_t)warpM * PITCH64;
    const uint32_t boff = (uint32_t)(((lane & 7) + ((lane >> 4) & 1) * 8) * PITCH64
                        + ((lane >> 3) & 1) * 16)
                        + (uint32_t)warpN * PITCH64 + OFF_B64;

    float acc[4][8][4];
#pragma unroll
    for (int mi = 0; mi < 4; mi++)
#pragma unroll
        for (int ni = 0; ni < 8; ni++)
#pragma unroll
            for (int r = 0; r < 4; r++) acc[mi][ni][r] = 0.f;

    auto load_stage = [&](int s, int k0) {
        const uint32_t base = sb + (uint32_t)s * STAGE64;
#pragma unroll
        for (int pp = 0; pp < 8; pp++) {
            int c = tid + pp * 128;        // 0..1023
            int row = c >> 3, col = c & 7;
            uint32_t soff = row * PITCH64 + col * 16;
            cp16(base + soff,            A + (size_t)(rowBase + row) * DD + k0 + col * 8);
            cp16(base + OFF_B64 + soff,  B + (size_t)(colBase + row) * DD + k0 + col * 8);
        }
        asm volatile("cp.async.commit_group;");
    };

    load_stage(0, 0);
    load_stage(1, 64);

    const int NCHUNK = DD / 64;   // 32
    int stageIdx = 0;
    for (int cc = 0; cc < NCHUNK; cc++) {
        if (cc + 2 < NCHUNK) {
            int s2 = stageIdx + 2; if (s2 >= 3) s2 -= 3;
            load_stage(s2, (cc + 2) * 64);
            asm volatile("cp.async.wait_group 2;");
        } else if (cc + 1 < NCHUNK) {
            asm volatile("cp.async.wait_group 1;");
        } else {
            asm volatile("cp.async.wait_group 0;");
        }
        __syncthreads();

        const uint32_t stg = sb + (uint32_t)stageIdx * STAGE64;
#pragma unroll
        for (int kk = 0; kk < 4; kk++) {
            const uint32_t kb = kk * 32;
            uint32_t ah[4][4], bq[4][4];
#pragma unroll
            for (int mi = 0; mi < 4; mi++)
                LDSM_X4(ah[mi], stg + aoff + (uint32_t)(mi * 16) * PITCH64 + kb);
#pragma unroll
            for (int np = 0; np < 4; np++)
                LDSM_X4(bq[np], stg + boff + (uint32_t)(np * 16) * PITCH64 + kb);
#pragma unroll
            for (int mi = 0; mi < 4; mi++)
#pragma unroll
                for (int ni = 0; ni < 8; ni++)
                    MMA_F16(acc[mi][ni], ah[mi], (&bq[ni >> 1][(ni & 1) * 2]));
        }
        __syncthreads();
        if (++stageIdx == 3) stageIdx = 0;
    }

    const int Mstore = p.Mstore;
    if (p.C16[z]) {
        __half* __restrict__ O = p.C16[z];
#pragma unroll
        for (int mi = 0; mi < 4; mi++) {
            int gr0 = rowBase + warpM + mi * 16 + quad;
            int gr1 = gr0 + 8;
#pragma unroll
            for (int ni = 0; ni < 8; ni++) {
                int gc = colBase + warpN + ni * 8 + four * 2;
                *(__half2*)&O[(size_t)gr0 * DD + gc] =
                    __floats2half2_rn(acc[mi][ni][0], acc[mi][ni][1]);
                *(__half2*)&O[(size_t)gr1 * DD + gc] =
                    __floats2half2_rn(acc[mi][ni][2], acc[mi][ni][3]);
            }
        }
    } else {
        const float* __restrict__ bias = p.bias[z];
        float* __restrict__ C = p.C[z];
#pragma unroll
        for (int mi = 0; mi < 4; mi++) {
            int gr0 = rowBase + warpM + mi * 16 + quad;
            int gr1 = gr0 + 8;
#pragma unroll
            for (int ni = 0; ni < 8; ni++) {
                int gc = colBase + warpN + ni * 8 + four * 2;
                float b0 = bias[gc], b1 = bias[gc + 1];
                if (gr0 < Mstore)
                    *(float2*)&C[(size_t)gr0 * DD + gc] =
                        make_float2(acc[mi][ni][0] + b0, acc[mi][ni][1] + b1);
                if (gr1 < Mstore)
                    *(float2*)&C[(size_t)gr1 * DD + gc] =
                        make_float2(acc[mi][ni][2] + b0, acc[mi][ni][3] + b1);
            }
        }
    }
}

// ============ final reduce ============
__global__ void reduce_final(float* __restrict__ out, const float* __restrict__ bias)
{
    const int r = blockIdx.y;
    const int c = blockIdx.x * 256 + threadIdx.x;
    float a = 0.f;
#pragma unroll
    for (int s = 0; s < 8; s++) a += g_part[(size_t)s * 128 * DD + (size_t)r * DD + c];
    out[(size_t)r * DD + c] = a + bias[c] * g_S[r];
}

// ============ stage-1 window attention: banded dots of P vs fc ============
__global__ void __launch_bounds__(512) attn1_kernel(const float* __restrict__ fc)
{
    const int b = blockIdx.x;
    const int tid = threadIdx.x;
    const int warp = tid >> 5, lane = tid & 31;
    const int r0 = warp * 4;

    __shared__ float Qc[64][65];
    __shared__ float Kc[64][65];
    __shared__ float band[64][15];

    float acc[60];
#pragma unroll
    for (int e = 0; e < 60; e++) acc[e] = 0.f;

    for (int ch = 0; ch < 32; ch++) {
#pragma unroll
        for (int pp = 0; pp < 2; pp++) {
            int f4 = tid + pp * 512;
            int row = f4 >> 4, q = f4 & 15;
            const float4 v = *(const float4*)(g_P + ((size_t)b * NN + row) * DD + ch * 64 + q * 4);
            const float4 u = *(const float4*)(fc  + ((size_t)b * NN + row) * DD + ch * 64 + q * 4);
            Qc[row][q*4+0] = v.x; Qc[row][q*4+1] = v.y; Qc[row][q*4+2] = v.z; Qc[row][q*4+3] = v.w;
            Kc[row][q*4+0] = u.x; Kc[row][q*4+1] = u.y; Kc[row][q*4+2] = u.z; Kc[row][q*4+3] = u.w;
        }
        __syncthreads();
#pragma unroll
        for (int t = 0; t < 2; t++) {
            int dd = lane + t * 32;
            float qv[4];
#pragma unroll
            for (int i = 0; i < 4; i++) qv[i] = Qc[r0 + i][dd];
            float kv[18];
#pragma unroll
            for (int jj = 0; jj < 18; jj++) {
                int cc = r0 - 7 + jj;
                kv[jj] = (cc >= 0 && cc < 64) ? Kc[cc][dd] : 0.f;
            }
#pragma unroll
            for (int i = 0; i < 4; i++)
#pragma unroll
                for (int d5 = 0; d5 < 15; d5++)
                    acc[i * 15 + d5] += qv[i] * kv[i + d5];
        }
        __syncthreads();
    }
#pragma unroll
    for (int e = 0; e < 60; e++) {
#pragma unroll
        for (int off = 16; off; off >>= 1)
            acc[e] += __shfl_xor_sync(0xFFFFFFFFu, acc[e], off);
    }
    if (lane == 0) {
#pragma unroll
        for (int i = 0; i < 4; i++)
#pragma unroll
            for (int d5 = 0; d5 < 15; d5++) {
                int r = r0 + i, cc = r + d5 - 7;
                if (cc >= 0 && cc < 64) band[r][d5] = acc[i * 15 + d5];
            }
    }
    __syncthreads();

    if (tid < WW) {
        int w = tid;
        float col[8];
#pragma unroll
        for (int j = 0; j < 8; j++) col[j] = 0.f;
#pragma unroll
        for (int i = 0; i < 8; i++) {
            float s[8], m = -1e30f;
#pragma unroll
            for (int j = 0; j < 8; j++) {
                s[j] = band[w + i][j - i + 7] * SCALE;
                m = fmaxf(m, s[j]);
            }
            float e[8], sum = 0.f;
#pragma unroll
            for (int j = 0; j < 8; j++) { e[j] = __expf(s[j] - m); sum += e[j]; }
            float inv = 1.f / sum;
#pragma unroll
            for (int j = 0; j < 8; j++) col[j] += e[j] * inv;
        }
#pragma unroll
        for (int j = 0; j < 8; j++)
            g_c[((size_t)b * WW + w) * NBW + j] = col[j];
    }
}

// ============ h = downsample + nsa ============
__global__ void coef_kernel(const float* __restrict__ fc, const float* __restrict__ ds_w,
                            const float* __restrict__ ds_b)
{
    const int b = blockIdx.y;
    const int d = blockIdx.x * 128 + threadIdx.x;

    __shared__ float sA[WW * NN];
    __shared__ float sB[WW * NN];
    for (int i = threadIdx.x; i < WW * NN; i += 128) { sA[i] = ds_w[i]; sB[i] = 0.f; }
    __syncthreads();
    for (int i = threadIdx.x; i < WW * NBW; i += 128) {
        int w = i / NBW, j = i % NBW;
        sB[w * NN + w + j] = g_c[((size_t)b * WW + w) * NBW + j];
    }
    __syncthreads();

    const float* fcb = fc + (size_t)b * NN * DD + d;
    const float* vnb = g_Vn + (size_t)b * NN * DD + d;

    float acc[WW];
#pragma unroll
    for (int w = 0; w < WW; w++) acc[w] = 0.f;
    for (int n = 0; n < NN; n++) {
        float fv = fcb[(size_t)n * DD];
        float vv = vnb[(size_t)n * DD];
#pragma unroll
        for (int w = 0; w < WW; w++)
            acc[w] += fv * sA[w * NN + n] + vv * sB[w * NN + n];
    }
    float* hb = g_h + (size_t)b * WW * DD + d;
#pragma unroll
    for (int w = 0; w < WW; w++)
        hb[(size_t)w * DD] = acc[w] + ds_b[w];
}

// ============ LayerNorm -> bf16 hi/lo + fp16 ============
__global__ void ln_split_kernel(const float* __restrict__ g, const float* __restrict__ beta)
{
    const int row = blockIdx.x;
    const int tid = threadIdx.x;
    const float* hr = g_h + (size_t)row * DD;

    float v[8], s = 0.f, s2 = 0.f;
#pragma unroll
    for (int p = 0; p < 8; p++) {
        v[p] = hr[tid + p * 256];
        s += v[p]; s2 += v[p] * v[p];
    }
#pragma unroll
    for (int off = 16; off; off >>= 1) {
        s  += __shfl_xor_sync(0xFFFFFFFFu, s, off);
        s2 += __shfl_xor_sync(0xFFFFFFFFu, s2, off);
    }
    __shared__ float ws[8], ws2[8], smu, sinv;
    const int warp = tid >> 5, lane = tid & 31;
    if (lane == 0) { ws[warp] = s; ws2[warp] = s2; }
    __syncthreads();
    if (warp == 0) {
        float a  = (lane < 8) ? ws[lane]  : 0.f;
        float a2 = (lane < 8) ? ws2[lane] : 0.f;
#pragma unroll
        for (int off = 4; off; off >>= 1) {
            a  += __shfl_xor_sync(0xFFFFFFFFu, a, off);
            a2 += __shfl_xor_sync(0xFFFFFFFFu, a2, off);
        }
        if (lane == 0) {
            float mu = a / (float)DD;
            smu = mu; sinv = rsqrtf(a2 / (float)DD - mu * mu + LNEPS);
        }
    }
    __syncthreads();
    float mu = smu, inv = sinv;
#pragma unroll
    for (int p = 0; p < 8; p++) {
        int d = tid + p * 256;
        float y = (v[p] - mu) * inv * g[d] + beta[d];
        __nv_bfloat16 h = __float2bfloat16(y);
        g_hn_hi[(size_t)row * DD + d] = h;
        g_hn_lo[(size_t)row * DD + d] = __float2bfloat16(y - __bfloat162float(h));
        g_hn16[(size_t)row * DD + d]  = __float2half(y);
    }
}

// ============ stage-2 scores: P2 vs hn16, K-split 64x64 ============
__global__ void dot2_kernel()
{
    const int sl = blockIdx.x, b = blockIdx.y;
    const int tid = threadIdx.x;
    const int ty = tid >> 4, tx = tid & 15;

    __shared__ float Qc[64][33];
    __shared__ float Kc[64][33];

    float acc[4][4];
#pragma unroll
    for (int i = 0; i < 4; i++)
#pragma unroll
        for (int j = 0; j < 4; j++) acc[i][j] = 0.f;

    const size_t rb = (size_t)b * WW;
    for (int ch = 0; ch < 16; ch++) {
        int k0 = sl * 512 + ch * 32;
#pragma unroll
        for (int pq = 0; pq < 2; pq++) {
            int idx = tid + pq * 256;
            int row = idx >> 3, q = idx & 7;
            float4 v = *(const float4*)(g_P2 + (rb + row) * DD + k0 + q * 4);
            Qc[row][q*4+0] = v.x; Qc[row][q*4+1] = v.y; Qc[row][q*4+2] = v.z; Qc[row][q*4+3] = v.w;
        }
        {
            int row = tid >> 2, q = tid & 3;
            const uint4 hv = *(const uint4*)(g_hn16 + (rb + row) * DD + k0 + q * 8);
            const __half* hp = (const __half*)&hv;
#pragma unroll
            for (int e = 0; e < 8; e++)
                Kc[row][q*8+e] = __half2float(hp[e]);
        }
        __syncthreads();
#pragma unroll
        for (int d = 0; d < 32; d++) {
            float ra[4], rv[4];
#pragma unroll
            for (int i = 0; i < 4; i++) ra[i] = Qc[ty * 4 + i][d];
#pragma unroll
            for (int j = 0; j < 4; j++) rv[j] = Kc[tx * 4 + j][d];
#pragma unroll
            for (int i = 0; i < 4; i++)
#pragma unroll
                for (int j = 0; j < 4; j++) acc[i][j] += ra[i] * rv[j];
        }
        __syncthreads();
    }
#pragma unroll
    for (int i = 0; i < 4; i++)
#pragma unroll
        for (int j = 0; j < 4; j++)
            g_dot2[(((size_t)sl * BB + b) * 64 + ty * 4 + i) * 64 + tx * 4 + j] = acc[i][j];
}

// ============ stage-2 softmax column sums + fused hbar ============
__global__ void cw2_kernel()
{
    const int b = blockIdx.x;
    const int tid = threadIdx.x;
    __shared__ float s[WW * 64];
    __shared__ float rmax[WW], rinv[WW], cs[WW];

    for (int idx = tid; idx < WW * 64; idx += 256) {
        int i = idx >> 6, j = idx & 63;
        float v = 0.f;
        if (j < WW) {
#pragma unroll
            for (int sl = 0; sl < 4; sl++)
                v += g_dot2[(((size_t)sl * BB + b) * 64 + i) * 64 + j];
        }
        s[idx] = v * SCALE;
    }
    __syncthreads();
    if (tid < WW) {
        float m = -1e30f;
        for (int j = 0; j < WW; j++) m = fmaxf(m, s[tid * 64 + j]);
        float sum = 0.f;
        for (int j = 0; j < WW; j++) sum += __expf(s[tid * 64 + j] - m);
        rmax[tid] = m; rinv[tid] = 1.f / sum;
    }
    __syncthreads();
    if (tid < WW) {
        float col = 0.f;
        for (int i = 0; i < WW; i++)
            col += __expf(s[i * 64 + tid] - rmax[i]) * rinv[i];
        cs[tid] = col;
    }
    __syncthreads();
    if (tid == 0) {
        float t = 0.f;
        for (int j = 0; j < WW; j++) t += cs[j];
        g_S[b] = t;
    }

    // fused hbar: hb[b][d] = sum_j cs[j] * hn[b][j][d]  (hi+lo), then split
#pragma unroll
    for (int dc = 0; dc < 8; dc++) {
        int d = dc * 256 + tid;
        float a = 0.f;
#pragma unroll 8
        for (int j = 0; j < WW; j++) {
            size_t r = (size_t)(b * WW + j) * DD + d;
            a += cs[j] * (__bfloat162float(g_hn_hi[r]) + __bfloat162float(g_hn_lo[r]));
        }
        __nv_bfloat16 h = __float2bfloat16(a);
        g_hb_hi[(size_t)b * DD + d] = h;
        g_hb_lo[(size_t)b * DD + d] = __float2bfloat16(a - __bfloat162float(h));
    }
}

// ============ launch ============
extern "C" void kernel_launch(void* const* d_in, const int* in_sizes, int n_in,
                              void* d_out, int out_size)
{
    (void)in_sizes; (void)n_in; (void)out_size;

    const float* fc     = (const float*)d_in[0];
    const float* nsa_wq = (const float*)d_in[1];
    const float* nsa_bq = (const float*)d_in[2];
    const float* nsa_wk = (const float*)d_in[3];
    const float* nsa_wv = (const float*)d_in[5];
    const float* nsa_bv = (const float*)d_in[6];
    const float* ds_w   = (const float*)d_in[7];
    const float* ds_b   = (const float*)d_in[8];
    const float* ln_g   = (const float*)d_in[9];
    const float* ln_b   = (const float*)d_in[10];
    const float* sa_wq  = (const float*)d_in[11];
    const float* sa_bq  = (const float*)d_in[12];
    const float* sa_wk  = (const float*)d_in[13];
    const float* sa_wv  = (const float*)d_in[15];
    const float* sa_bv  = (const float*)d_in[16];
    float* out = (float*)d_out;

    float *P, *Vn, *P2, *uu, *part;
    __nv_bfloat16 *wv2h, *wv2l, *hbh, *hbl;
    __half *fc16, *wT16, *wv16, *G16, *hn16;
    cudaGetSymbolAddress((void**)&P,    g_P);
    cudaGetSymbolAddress((void**)&Vn,   g_Vn);
    cudaGetSymbolAddress((void**)&P2,   g_P2);
    cudaGetSymbolAddress((void**)&uu,   g_u);
    cudaGetSymbolAddress((void**)&part, g_part);
    cudaGetSymbolAddress((void**)&fc16, g_fc16);
    cudaGetSymbolAddress((void**)&wT16, g_wT16);
    cudaGetSymbolAddress((void**)&wv16, g_wv16);
    cudaGetSymbolAddress((void**)&wv2h, g_wv2_hi);
    cudaGetSymbolAddress((void**)&wv2l, g_wv2_lo);
    cudaGetSymbolAddress((void**)&G16,  g_G16);
    cudaGetSymbolAddress((void**)&hn16, g_hn16);
    cudaGetSymbolAddress((void**)&hbh,  g_hb_hi);
    cudaGetSymbolAddress((void**)&hbl,  g_hb_lo);

    cudaFuncSetAttribute(gemm_mma_b, cudaFuncAttributeMaxDynamicSharedMemorySize, 2 * STAGE_BYTES);
    cudaFuncSetAttribute(gemm_f16,   cudaFuncAttributeMaxDynamicSharedMemorySize, 3 * STAGE64);

    // --- launches 1-3 ---
    split_all16<<<(BB*NN*DD + 2*(int)NW + 255)/256, 256>>>(fc, nsa_wv, sa_wv);
    {
        SplitTSrc st = { { nsa_wq, nsa_wk, sa_wq, sa_wk } };
        splitT_kernel<<<dim3(32, 32, 4), dim3(32, 8)>>>(st);
    }
    u_part<<<dim3(8, 16, 2), 256>>>(nsa_bq, nsa_wk, sa_bq, sa_wk);
    // --- launch 4 (ncu capture slot): Gram GEMMs ---
    {
        Gemm16Batch p = {};
        p.A[0] = wT16 + 1*NW; p.B[0] = wT16 + 0*NW; p.C16[0] = G16;
        p.A[1] = wT16 + 3*NW; p.B[1] = wT16 + 2*NW; p.C16[1] = G16 + NW;
        p.Mstore = DD;
        gemm_f16<<<dim3(16, 16, 2), 128, 3 * STAGE64>>>(p);
    }
    u_reduce<<<dim3(8, 2), 256>>>();

    // z-batched: P = fc16 @ G16^T + u1;  Vn = fc16 @ wv16^T + bv
    {
        Gemm16Batch p = {};
        p.A[0] = fc16; p.B[0] = G16;  p.bias[0] = uu;     p.C[0] = P;
        p.A[1] = fc16; p.B[1] = wv16; p.bias[1] = nsa_bv; p.C[1] = Vn;
        p.Mstore = BB * NN;
        gemm_f16<<<dim3(16, 32, 2), 128, 3 * STAGE64>>>(p);
    }

    attn1_kernel<<<BB, 512>>>(fc);
    coef_kernel<<<dim3(DD / 128, BB), 128>>>(fc, ds_w, ds_b);
    ln_split_kernel<<<BB * WW, 256>>>(ln_g, ln_b);

    // P2 = hn16 @ G2^T + u2
    {
        Gemm16Batch p = {};
        p.A[0] = hn16; p.B[0] = G16 + NW; p.bias[0] = uu + DD; p.C[0] = P2;
        p.Mstore = MPAD2;
        gemm_f16<<<dim3(16, 29, 1), 128, 3 * STAGE64>>>(p);
    }

    dot2_kernel<<<dim3(4, BB), 256>>>();
    cw2_kernel<<<BB, 256>>>();

    // final: out = hbar @ Wv2^T + S[b]*bias (3-product bf16, k-split 8, reduce)
    {
        GemmBatch p = {};
        p.Ah = hbh; p.Al = hbl; p.Bh = wv2h; p.Bl = wv2l; p.C = part;
        p.kSplit = 8;
        gemm_mma_b<<<dim3(16, 1, 8), 128, 2 * STAGE_BYTES>>>(p);
    }
    reduce_final<<<dim3(8, BB), 256>>>(out, sa_bv);
}

// round 14
// speedup vs baseline: 1.0644x; 1.0644x over previous
#include <cuda_runtime.h>
#include <cuda_bf16.h>
#include <cuda_fp16.h>
#include <cstdint>
#include <math.h>

#define BB 64
#define NN 64
#define DD 2048
#define NBW 8
#define WW 57
#define MPAD2 3712
#define SCALE 0.02209708691207961f
#define LNEPS 1e-5f
#define NW ((size_t)DD * DD)

// ============ scratch ============
__device__ float g_P  [BB * NN * DD];
__device__ float g_Vn [BB * NN * DD];
__device__ float g_h  [BB * WW * DD];
__device__ float g_P2 [MPAD2 * DD];
__device__ float g_c  [BB * WW * NBW];
__device__ float g_S  [BB];
__device__ float g_dot2[4 * BB * 64 * 64];
__device__ float g_u  [2 * DD];
__device__ float g_upart[2 * 16 * DD];
__device__ float g_part[8 * 128 * DD];

__device__ __align__(16) __half        g_fc16 [BB * NN * DD];
__device__ __align__(16) __half        g_wT16 [4 * NW];   // WqT, WkT, Wq2T, Wk2T
__device__ __align__(16) __half        g_wv16 [NW];       // Wv (stage 1, fp16)
__device__ __align__(16) __nv_bfloat16 g_wv2_hi[NW];      // Wv2 (final, bf16 hi/lo)
__device__ __align__(16) __nv_bfloat16 g_wv2_lo[NW];
__device__ __align__(16) __half        g_G16  [2 * NW];   // Gram matrices
__device__ __align__(16) __nv_bfloat16 g_hn_hi[MPAD2 * DD];  // rows >=3648 stay zero
__device__ __align__(16) __nv_bfloat16 g_hn_lo[MPAD2 * DD];
__device__ __align__(16) __half        g_hn16 [MPAD2 * DD];
__device__ __align__(16) __nv_bfloat16 g_hb_hi[128 * DD];    // rows >=64 stay zero
__device__ __align__(16) __nv_bfloat16 g_hb_lo[128 * DD];

// ============ merged splits: fc->fp16, Wv->fp16, Wv2->bf16 hi/lo ============
__global__ void split_all16(const float* __restrict__ fc, const float* __restrict__ wv,
                            const float* __restrict__ wv2)
{
    int i = blockIdx.x * 256 + threadIdx.x;
    const int NFC = BB * NN * DD;
    const int NWI = (int)NW;
    if (i < NFC) {
        g_fc16[i] = __float2half(fc[i]);
    } else if (i < NFC + NWI) {
        int j = i - NFC;
        g_wv16[j] = __float2half(wv[j]);
    } else {
        int j = i - NFC - NWI;
        float v = wv2[j];
        __nv_bfloat16 h = __float2bfloat16(v);
        g_wv2_hi[j] = h;
        g_wv2_lo[j] = __float2bfloat16(v - __bfloat162float(h));
    }
}

// transpose to fp16 with coalesced half2 stores: wT16[z][i][m] = W[m][i]
struct SplitTSrc { const float* W[4]; };
__global__ void splitT_kernel(const __grid_constant__ SplitTSrc s)
{
    const int z = blockIdx.z;
    const float* __restrict__ W = s.W[z];
    __half* __restrict__ o = g_wT16 + (size_t)z * NW;
    __shared__ float t[64][65];
    const int m0 = blockIdx.y * 64, i0 = blockIdx.x * 64;
    const int tx = threadIdx.x, ty = threadIdx.y;  // 32, 8
#pragma unroll
    for (int rr = ty; rr < 64; rr += 8) {
        t[rr][tx]      = W[(size_t)(m0 + rr) * DD + i0 + tx];
        t[rr][tx + 32] = W[(size_t)(m0 + rr) * DD + i0 + tx + 32];
    }
    __syncthreads();
#pragma unroll
    for (int ii = ty; ii < 64; ii += 8) {
        __half2 v = __floats2half2_rn(t[tx * 2][ii], t[tx * 2 + 1][ii]);
        *(__half2*)(o + (size_t)(i0 + ii) * DD + m0 + tx * 2) = v;
    }
}

// ============ u[z][j] = sum_m bq[m] * Wk[m][j] ============
__global__ void u_part(const float* __restrict__ b1, const float* __restrict__ W1,
                       const float* __restrict__ b2, const float* __restrict__ W2)
{
    const int z = blockIdx.z;
    const float* __restrict__ b = z ? b2 : b1;
    const float* __restrict__ W = z ? W2 : W1;
    const int j = blockIdx.x * 256 + threadIdx.x;
    const int m0 = blockIdx.y * 128;
    float a = 0.f;
    for (int m = m0; m < m0 + 128; m++) a += b[m] * W[(size_t)m * DD + j];
    g_upart[((size_t)z * 16 + blockIdx.y) * DD + j] = a;
}
__global__ void u_reduce()
{
    const int z = blockIdx.y;
    const int j = blockIdx.x * 256 + threadIdx.x;
    float a = 0.f;
#pragma unroll
    for (int s = 0; s < 16; s++) a += g_upart[((size_t)z * 16 + s) * DD + j];
    g_u[z * DD + j] = a;
}

// ============ common GEMM plumbing ============
#define PITCH 80
__device__ __forceinline__ void cp16(uint32_t saddr, const void* gaddr) {
    asm volatile("cp.async.cg.shared.global [%0], [%1], 16;" :: "r"(saddr), "l"(gaddr));
}
__device__ __forceinline__ uint32_t smem_u32(const void* p) {
    uint32_t a;
    asm("{ .reg .u64 t; cvta.to.shared.u64 t, %1; cvt.u32.u64 %0, t; }" : "=r"(a) : "l"(p));
    return a;
}
#define MMA_BF16(d, a, b) \
    asm volatile("mma.sync.aligned.m16n8k16.row.col.f32.bf16.bf16.f32 " \
        "{%0,%1,%2,%3},{%4,%5,%6,%7},{%8,%9},{%0,%1,%2,%3};" \
        : "+f"((d)[0]), "+f"((d)[1]), "+f"((d)[2]), "+f"((d)[3]) \
        : "r"((a)[0]), "r"((a)[1]), "r"((a)[2]), "r"((a)[3]), "r"((b)[0]), "r"((b)[1]))
#define MMA_F16(d, a, b) \
    asm volatile("mma.sync.aligned.m16n8k16.row.col.f32.f16.f16.f32 " \
        "{%0,%1,%2,%3},{%4,%5,%6,%7},{%8,%9},{%0,%1,%2,%3};" \
        : "+f"((d)[0]), "+f"((d)[1]), "+f"((d)[2]), "+f"((d)[3]) \
        : "r"((a)[0]), "r"((a)[1]), "r"((a)[2]), "r"((a)[3]), "r"((b)[0]), "r"((b)[1]))
#define LDSM_X4(r, addr) \
    asm volatile("ldmatrix.sync.aligned.m8n8.x4.shared.b16 {%0,%1,%2,%3}, [%4];" \
        : "=r"((r)[0]), "=r"((r)[1]), "=r"((r)[2]), "=r"((r)[3]) : "r"(addr))

__device__ __forceinline__ uint32_t a_lane_off(int lane) {
    return (uint32_t)((lane & 15) * PITCH + ((lane >> 4) & 1) * 16);
}
__device__ __forceinline__ uint32_t b_lane_off(int lane) {
    return (uint32_t)(((lane & 7) + ((lane >> 4) & 1) * 8) * PITCH + ((lane >> 3) & 1) * 16);
}

// ============ 3-product bf16 GEMM (final projection only), k-split ============
#define STAGE_BYTES 40960
#define OFF_AH 0
#define OFF_AL 10240
#define OFF_BH 20480
#define OFF_BL 30720

struct GemmBatch {
    const __nv_bfloat16* Ah;
    const __nv_bfloat16* Al;
    const __nv_bfloat16* Bh;
    const __nv_bfloat16* Bl;
    float* C;
    int kSplit;
};

__global__ void __launch_bounds__(128, 2) gemm_mma_b(const __grid_constant__ GemmBatch p)
{
    extern __shared__ char smem[];
    const uint32_t sb = smem_u32(smem);
    const int tid = threadIdx.x;
    const int wid = tid >> 5, lane = tid & 31;
    const int quad = lane >> 2, four = lane & 3;
    const int rowBase = blockIdx.y * 128, colBase = blockIdx.x * 128;
    const int warpM = (wid >> 1) * 64, warpN = (wid & 1) * 64;
    const int slice = blockIdx.z;
    const int chunksPer = (DD / 32) / p.kSplit;
    const int c0 = slice * chunksPer;

    const __nv_bfloat16* __restrict__ Ahi = p.Ah;
    const __nv_bfloat16* __restrict__ Alo = p.Al;
    const __nv_bfloat16* __restrict__ Bhi = p.Bh;
    const __nv_bfloat16* __restrict__ Blo = p.Bl;

    const uint32_t aoff = a_lane_off(lane) + (uint32_t)warpM * PITCH;
    const uint32_t boff = b_lane_off(lane) + (uint32_t)warpN * PITCH;

    float acc[4][8][4];
#pragma unroll
    for (int mi = 0; mi < 4; mi++)
#pragma unroll
        for (int ni = 0; ni < 8; ni++)
#pragma unroll
            for (int r = 0; r < 4; r++) acc[mi][ni][r] = 0.f;

    auto load_stage = [&](int s, int k0) {
        const uint32_t base = sb + (uint32_t)s * STAGE_BYTES;
#pragma unroll
        for (int pp = 0; pp < 4; pp++) {
            int c = tid + pp * 128;
            int row = c >> 2, col = c & 3;
            uint32_t soff = row * PITCH + col * 16;
            size_t ga = (size_t)(rowBase + row) * DD + k0 + col * 8;
            size_t gb = (size_t)(colBase + row) * DD + k0 + col * 8;
            cp16(base + OFF_AH + soff, Ahi + ga);
            cp16(base + OFF_AL + soff, Alo + ga);
            cp16(base + OFF_BH + soff, Bhi + gb);
            cp16(base + OFF_BL + soff, Blo + gb);
        }
        asm volatile("cp.async.commit_group;");
    };

    load_stage(0, c0 * 32);

    for (int cc = 0; cc < chunksPer; cc++) {
        if (cc + 1 < chunksPer) {
            load_stage((cc + 1) & 1, (c0 + cc + 1) * 32);
            asm volatile("cp.async.wait_group 1;");
        } else {
            asm volatile("cp.async.wait_group 0;");
        }
        __syncthreads();

        const uint32_t stg = sb + (uint32_t)(cc & 1) * STAGE_BYTES;
#pragma unroll
        for (int kk = 0; kk < 2; kk++) {
            const uint32_t kb = kk * 32;
            uint32_t ah[4][4], al[4][4], bhq[4][4], blq[4][4];
#pragma unroll
            for (int mi = 0; mi < 4; mi++) {
                uint32_t ad = stg + aoff + (uint32_t)(mi * 16) * PITCH + kb;
                LDSM_X4(ah[mi], ad + OFF_AH);
                LDSM_X4(al[mi], ad + OFF_AL);
            }
#pragma unroll
            for (int np = 0; np < 4; np++) {
                uint32_t bd = stg + boff + (uint32_t)(np * 16) * PITCH + kb;
                LDSM_X4(bhq[np], bd + OFF_BH);
                LDSM_X4(blq[np], bd + OFF_BL);
            }
#pragma unroll
            for (int mi = 0; mi < 4; mi++)
#pragma unroll
                for (int ni = 0; ni < 8; ni++)
                    MMA_BF16(acc[mi][ni], ah[mi], (&bhq[ni >> 1][(ni & 1) * 2]));
#pragma unroll
            for (int mi = 0; mi < 4; mi++)
#pragma unroll
                for (int ni = 0; ni < 8; ni++)
                    MMA_BF16(acc[mi][ni], ah[mi], (&blq[ni >> 1][(ni & 1) * 2]));
#pragma unroll
            for (int mi = 0; mi < 4; mi++)
#pragma unroll
                for (int ni = 0; ni < 8; ni++)
                    MMA_BF16(acc[mi][ni], al[mi], (&bhq[ni >> 1][(ni & 1) * 2]));
        }
        __syncthreads();
    }

    float* __restrict__ Cp = p.C + (size_t)slice * (gridDim.y * 128) * DD;
#pragma unroll
    for (int mi = 0; mi < 4; mi++) {
        int gr0 = rowBase + warpM + mi * 16 + quad;
        int gr1 = gr0 + 8;
#pragma unroll
        for (int ni = 0; ni < 8; ni++) {
            int gc = colBase + warpN + ni * 8 + four * 2;
            *(float2*)&Cp[(size_t)gr0 * DD + gc] = make_float2(acc[mi][ni][0], acc[mi][ni][1]);
            *(float2*)&Cp[(size_t)gr1 * DD + gc] = make_float2(acc[mi][ni][2], acc[mi][ni][3]);
        }
    }
}

// ============ single-product fp16 GEMM, 128 threads, k-chunk 32, 3-stage ============
#define STAGE16 20480
#define OFF_B16 10240

struct Gemm16Batch {
    const __half* A[2];
    const __half* B[2];
    const float* bias[2];
    float* C[2];
    __half* C16[2];
    int Mstore;
};

__global__ void __launch_bounds__(128, 2) gemm_f16(const __grid_constant__ Gemm16Batch p)
{
    extern __shared__ char smem[];
    const uint32_t sb = smem_u32(smem);
    const int tid = threadIdx.x;
    const int wid = tid >> 5, lane = tid & 31;
    const int quad = lane >> 2, four = lane & 3;
    const int rowBase = blockIdx.y * 128, colBase = blockIdx.x * 128;
    const int warpM = (wid >> 1) * 64, warpN = (wid & 1) * 64;
    const int z = blockIdx.z;

    const __half* __restrict__ A = p.A[z];
    const __half* __restrict__ B = p.B[z];

    const uint32_t aoff = a_lane_off(lane) + (uint32_t)warpM * PITCH;
    const uint32_t boff = b_lane_off(lane) + (uint32_t)warpN * PITCH + OFF_B16;

    float acc[4][8][4];
#pragma unroll
    for (int mi = 0; mi < 4; mi++)
#pragma unroll
        for (int ni = 0; ni < 8; ni++)
#pragma unroll
            for (int r = 0; r < 4; r++) acc[mi][ni][r] = 0.f;

    auto load_stage = [&](int s, int k0) {
        const uint32_t base = sb + (uint32_t)s * STAGE16;
#pragma unroll
        for (int pp = 0; pp < 4; pp++) {
            int c = tid + pp * 128;
            int row = c >> 2, col = c & 3;
            uint32_t soff = row * PITCH + col * 16;
            cp16(base + soff,            A + (size_t)(rowBase + row) * DD + k0 + col * 8);
            cp16(base + OFF_B16 + soff,  B + (size_t)(colBase + row) * DD + k0 + col * 8);
        }
        asm volatile("cp.async.commit_group;");
    };

    load_stage(0, 0);
    load_stage(1, 32);

    const int NCHUNK = DD / 32;
    int stageIdx = 0;
    for (int cc = 0; cc < NCHUNK; cc++) {
        if (cc + 2 < NCHUNK) {
            int s2 = stageIdx + 2; if (s2 >= 3) s2 -= 3;
            load_stage(s2, (cc + 2) * 32);
            asm volatile("cp.async.wait_group 2;");
        } else if (cc + 1 < NCHUNK) {
            asm volatile("cp.async.wait_group 1;");
        } else {
            asm volatile("cp.async.wait_group 0;");
        }
        __syncthreads();

        const uint32_t stg = sb + (uint32_t)stageIdx * STAGE16;
#pragma unroll
        for (int kk = 0; kk < 2; kk++) {
            const uint32_t kb = kk * 32;
            uint32_t ah[4][4], bq[4][4];
#pragma unroll
            for (int mi = 0; mi < 4; mi++)
                LDSM_X4(ah[mi], stg + aoff + (uint32_t)(mi * 16) * PITCH + kb);
#pragma unroll
            for (int np = 0; np < 4; np++)
                LDSM_X4(bq[np], stg + boff + (uint32_t)(np * 16) * PITCH + kb);
#pragma unroll
            for (int mi = 0; mi < 4; mi++)
#pragma unroll
                for (int ni = 0; ni < 8; ni++)
                    MMA_F16(acc[mi][ni], ah[mi], (&bq[ni >> 1][(ni & 1) * 2]));
        }
        __syncthreads();
        if (++stageIdx == 3) stageIdx = 0;
    }

    const int Mstore = p.Mstore;
    if (p.C16[z]) {
        __half* __restrict__ O = p.C16[z];
#pragma unroll
        for (int mi = 0; mi < 4; mi++) {
            int gr0 = rowBase + warpM + mi * 16 + quad;
            int gr1 = gr0 + 8;
#pragma unroll
            for (int ni = 0; ni < 8; ni++) {
                int gc = colBase + warpN + ni * 8 + four * 2;
                *(__half2*)&O[(size_t)gr0 * DD + gc] =
                    __floats2half2_rn(acc[mi][ni][0], acc[mi][ni][1]);
                *(__half2*)&O[(size_t)gr1 * DD + gc] =
                    __floats2half2_rn(acc[mi][ni][2], acc[mi][ni][3]);
            }
        }
    } else {
        const float* __restrict__ bias = p.bias[z];
        float* __restrict__ C = p.C[z];
#pragma unroll
        for (int mi = 0; mi < 4; mi++) {
            int gr0 = rowBase + warpM + mi * 16 + quad;
            int gr1 = gr0 + 8;
#pragma unroll
            for (int ni = 0; ni < 8; ni++) {
                int gc = colBase + warpN + ni * 8 + four * 2;
                float b0 = bias[gc], b1 = bias[gc + 1];
                if (gr0 < Mstore)
                    *(float2*)&C[(size_t)gr0 * DD + gc] =
                        make_float2(acc[mi][ni][0] + b0, acc[mi][ni][1] + b1);
                if (gr1 < Mstore)
                    *(float2*)&C[(size_t)gr1 * DD + gc] =
                        make_float2(acc[mi][ni][2] + b0, acc[mi][ni][3] + b1);
            }
        }
    }
}

// ============ final reduce ============
__global__ void reduce_final(float* __restrict__ out, const float* __restrict__ bias)
{
    const int r = blockIdx.y;
    const int c = blockIdx.x * 256 + threadIdx.x;
    float a = 0.f;
#pragma unroll
    for (int s = 0; s < 8; s++) a += g_part[(size_t)s * 128 * DD + (size_t)r * DD + c];
    out[(size_t)r * DD + c] = a + bias[c] * g_S[r];
}

// ============ stage-1 window attention: banded dots of P vs fc ============
__global__ void __launch_bounds__(512) attn1_kernel(const float* __restrict__ fc)
{
    const int b = blockIdx.x;
    const int tid = threadIdx.x;
    const int warp = tid >> 5, lane = tid & 31;
    const int r0 = warp * 4;

    __shared__ float Qc[64][65];
    __shared__ float Kc[64][65];
    __shared__ float band[64][15];

    float acc[60];
#pragma unroll
    for (int e = 0; e < 60; e++) acc[e] = 0.f;

    for (int ch = 0; ch < 32; ch++) {
#pragma unroll
        for (int pp = 0; pp < 2; pp++) {
            int f4 = tid + pp * 512;
            int row = f4 >> 4, q = f4 & 15;
            const float4 v = *(const float4*)(g_P + ((size_t)b * NN + row) * DD + ch * 64 + q * 4);
            const float4 u = *(const float4*)(fc  + ((size_t)b * NN + row) * DD + ch * 64 + q * 4);
            Qc[row][q*4+0] = v.x; Qc[row][q*4+1] = v.y; Qc[row][q*4+2] = v.z; Qc[row][q*4+3] = v.w;
            Kc[row][q*4+0] = u.x; Kc[row][q*4+1] = u.y; Kc[row][q*4+2] = u.z; Kc[row][q*4+3] = u.w;
        }
        __syncthreads();
#pragma unroll
        for (int t = 0; t < 2; t++) {
            int dd = lane + t * 32;
            float qv[4];
#pragma unroll
            for (int i = 0; i < 4; i++) qv[i] = Qc[r0 + i][dd];
            float kv[18];
#pragma unroll
            for (int jj = 0; jj < 18; jj++) {
                int cc = r0 - 7 + jj;
                kv[jj] = (cc >= 0 && cc < 64) ? Kc[cc][dd] : 0.f;
            }
#pragma unroll
            for (int i = 0; i < 4; i++)
#pragma unroll
                for (int d5 = 0; d5 < 15; d5++)
                    acc[i * 15 + d5] += qv[i] * kv[i + d5];
        }
        __syncthreads();
    }
#pragma unroll
    for (int e = 0; e < 60; e++) {
#pragma unroll
        for (int off = 16; off; off >>= 1)
            acc[e] += __shfl_xor_sync(0xFFFFFFFFu, acc[e], off);
    }
    if (lane == 0) {
#pragma unroll
        for (int i = 0; i < 4; i++)
#pragma unroll
            for (int d5 = 0; d5 < 15; d5++) {
                int r = r0 + i, cc = r + d5 - 7;
                if (cc >= 0 && cc < 64) band[r][d5] = acc[i * 15 + d5];
            }
    }
    __syncthreads();

    if (tid < WW) {
        int w = tid;
        float col[8];
#pragma unroll
        for (int j = 0; j < 8; j++) col[j] = 0.f;
#pragma unroll
        for (int i = 0; i < 8; i++) {
            float s[8], m = -1e30f;
#pragma unroll
            for (int j = 0; j < 8; j++) {
                s[j] = band[w + i][j - i + 7] * SCALE;
                m = fmaxf(m, s[j]);
            }
            float e[8], sum = 0.f;
#pragma unroll
            for (int j = 0; j < 8; j++) { e[j] = __expf(s[j] - m); sum += e[j]; }
            float inv = 1.f / sum;
#pragma unroll
            for (int j = 0; j < 8; j++) col[j] += e[j] * inv;
        }
#pragma unroll
        for (int j = 0; j < 8; j++)
            g_c[((size_t)b * WW + w) * NBW + j] = col[j];
    }
}

// ============ h = downsample + nsa ============
__global__ void coef_kernel(const float* __restrict__ fc, const float* __restrict__ ds_w,
                            const float* __restrict__ ds_b)
{
    const int b = blockIdx.y;
    const int d = blockIdx.x * 128 + threadIdx.x;

    __shared__ float sA[WW * NN];
    __shared__ float sB[WW * NN];
    for (int i = threadIdx.x; i < WW * NN; i += 128) { sA[i] = ds_w[i]; sB[i] = 0.f; }
    __syncthreads();
    for (int i = threadIdx.x; i < WW * NBW; i += 128) {
        int w = i / NBW, j = i % NBW;
        sB[w * NN + w + j] = g_c[((size_t)b * WW + w) * NBW + j];
    }
    __syncthreads();

    const float* fcb = fc + (size_t)b * NN * DD + d;
    const float* vnb = g_Vn + (size_t)b * NN * DD + d;

    float acc[WW];
#pragma unroll
    for (int w = 0; w < WW; w++) acc[w] = 0.f;
    for (int n = 0; n < NN; n++) {
        float fv = fcb[(size_t)n * DD];
        float vv = vnb[(size_t)n * DD];
#pragma unroll
        for (int w = 0; w < WW; w++)
            acc[w] += fv * sA[w * NN + n] + vv * sB[w * NN + n];
    }
    float* hb = g_h + (size_t)b * WW * DD + d;
#pragma unroll
    for (int w = 0; w < WW; w++)
        hb[(size_t)w * DD] = acc[w] + ds_b[w];
}

// ============ LayerNorm -> bf16 hi/lo + fp16 ============
__global__ void ln_split_kernel(const float* __restrict__ g, const float* __restrict__ beta)
{
    const int row = blockIdx.x;
    const int tid = threadIdx.x;
    const float* hr = g_h + (size_t)row * DD;

    float v[8], s = 0.f, s2 = 0.f;
#pragma unroll
    for (int p = 0; p < 8; p++) {
        v[p] = hr[tid + p * 256];
        s += v[p]; s2 += v[p] * v[p];
    }
#pragma unroll
    for (int off = 16; off; off >>= 1) {
        s  += __shfl_xor_sync(0xFFFFFFFFu, s, off);
        s2 += __shfl_xor_sync(0xFFFFFFFFu, s2, off);
    }
    __shared__ float ws[8], ws2[8], smu, sinv;
    const int warp = tid >> 5, lane = tid & 31;
    if (lane == 0) { ws[warp] = s; ws2[warp] = s2; }
    __syncthreads();
    if (warp == 0) {
        float a  = (lane < 8) ? ws[lane]  : 0.f;
        float a2 = (lane < 8) ? ws2[lane] : 0.f;
#pragma unroll
        for (int off = 4; off; off >>= 1) {
            a  += __shfl_xor_sync(0xFFFFFFFFu, a, off);
            a2 += __shfl_xor_sync(0xFFFFFFFFu, a2, off);
        }
        if (lane == 0) {
            float mu = a / (float)DD;
            smu = mu; sinv = rsqrtf(a2 / (float)DD - mu * mu + LNEPS);
        }
    }
    __syncthreads();
    float mu = smu, inv = sinv;
#pragma unroll
    for (int p = 0; p < 8; p++) {
        int d = tid + p * 256;
        float y = (v[p] - mu) * inv * g[d] + beta[d];
        __nv_bfloat16 h = __float2bfloat16(y);
        g_hn_hi[(size_t)row * DD + d] = h;
        g_hn_lo[(size_t)row * DD + d] = __float2bfloat16(y - __bfloat162float(h));
        g_hn16[(size_t)row * DD + d]  = __float2half(y);
    }
}

// ============ stage-2 scores: P2 vs hn16, K-split 64x64 ============
__global__ void dot2_kernel()
{
    const int sl = blockIdx.x, b = blockIdx.y;
    const int tid = threadIdx.x;
    const int ty = tid >> 4, tx = tid & 15;

    __shared__ float Qc[64][33];
    __shared__ float Kc[64][33];

    float acc[4][4];
#pragma unroll
    for (int i = 0; i < 4; i++)
#pragma unroll
        for (int j = 0; j < 4; j++) acc[i][j] = 0.f;

    const size_t rb = (size_t)b * WW;
    for (int ch = 0; ch < 16; ch++) {
        int k0 = sl * 512 + ch * 32;
#pragma unroll
        for (int pq = 0; pq < 2; pq++) {
            int idx = tid + pq * 256;
            int row = idx >> 3, q = idx & 7;
            float4 v = *(const float4*)(g_P2 + (rb + row) * DD + k0 + q * 4);
            Qc[row][q*4+0] = v.x; Qc[row][q*4+1] = v.y; Qc[row][q*4+2] = v.z; Qc[row][q*4+3] = v.w;
        }
        {
            int row = tid >> 2, q = tid & 3;
            const uint4 hv = *(const uint4*)(g_hn16 + (rb + row) * DD + k0 + q * 8);
            const __half* hp = (const __half*)&hv;
#pragma unroll
            for (int e = 0; e < 8; e++)
                Kc[row][q*8+e] = __half2float(hp[e]);
        }
        __syncthreads();
#pragma unroll
        for (int d = 0; d < 32; d++) {
            float ra[4], rv[4];
#pragma unroll
            for (int i = 0; i < 4; i++) ra[i] = Qc[ty * 4 + i][d];
#pragma unroll
            for (int j = 0; j < 4; j++) rv[j] = Kc[tx * 4 + j][d];
#pragma unroll
            for (int i = 0; i < 4; i++)
#pragma unroll
                for (int j = 0; j < 4; j++) acc[i][j] += ra[i] * rv[j];
        }
        __syncthreads();
    }
#pragma unroll
    for (int i = 0; i < 4; i++)
#pragma unroll
        for (int j = 0; j < 4; j++)
            g_dot2[(((size_t)sl * BB + b) * 64 + ty * 4 + i) * 64 + tx * 4 + j] = acc[i][j];
}

// ============ stage-2 softmax column sums + fused hbar ============
__global__ void cw2_kernel()
{
    const int b = blockIdx.x;
    const int tid = threadIdx.x;
    __shared__ float s[WW * 64];
    __shared__ float rmax[WW], rinv[WW], cs[WW];

    for (int idx = tid; idx < WW * 64; idx += 256) {
        int i = idx >> 6, j = idx & 63;
        float v = 0.f;
        if (j < WW) {
#pragma unroll
            for (int sl = 0; sl < 4; sl++)
                v += g_dot2[(((size_t)sl * BB + b) * 64 + i) * 64 + j];
        }
        s[idx] = v * SCALE;
    }
    __syncthreads();
    if (tid < WW) {
        float m = -1e30f;
        for (int j = 0; j < WW; j++) m = fmaxf(m, s[tid * 64 + j]);
        float sum = 0.f;
        for (int j = 0; j < WW; j++) sum += __expf(s[tid * 64 + j] - m);
        rmax[tid] = m; rinv[tid] = 1.f / sum;
    }
    __syncthreads();
    if (tid < WW) {
        float col = 0.f;
        for (int i = 0; i < WW; i++)
            col += __expf(s[i * 64 + tid] - rmax[i]) * rinv[i];
        cs[tid] = col;
    }
    __syncthreads();
    if (tid == 0) {
        float t = 0.f;
        for (int j = 0; j < WW; j++) t += cs[j];
        g_S[b] = t;
    }

    // fused hbar: hb[b][d] = sum_j cs[j] * hn[b][j][d]  (hi+lo), then split
#pragma unroll
    for (int dc = 0; dc < 8; dc++) {
        int d = dc * 256 + tid;
        float a = 0.f;
#pragma unroll 8
        for (int j = 0; j < WW; j++) {
            size_t r = (size_t)(b * WW + j) * DD + d;
            a += cs[j] * (__bfloat162float(g_hn_hi[r]) + __bfloat162float(g_hn_lo[r]));
        }
        __nv_bfloat16 h = __float2bfloat16(a);
        g_hb_hi[(size_t)b * DD + d] = h;
        g_hb_lo[(size_t)b * DD + d] = __float2bfloat16(a - __bfloat162float(h));
    }
}

// ============ launch ============
extern "C" void kernel_launch(void* const* d_in, const int* in_sizes, int n_in,
                              void* d_out, int out_size)
{
    (void)in_sizes; (void)n_in; (void)out_size;

    const float* fc     = (const float*)d_in[0];
    const float* nsa_wq = (const float*)d_in[1];
    const float* nsa_bq = (const float*)d_in[2];
    const float* nsa_wk = (const float*)d_in[3];
    const float* nsa_wv = (const float*)d_in[5];
    const float* nsa_bv = (const float*)d_in[6];
    const float* ds_w   = (const float*)d_in[7];
    const float* ds_b   = (const float*)d_in[8];
    const float* ln_g   = (const float*)d_in[9];
    const float* ln_b   = (const float*)d_in[10];
    const float* sa_wq  = (const float*)d_in[11];
    const float* sa_bq  = (const float*)d_in[12];
    const float* sa_wk  = (const float*)d_in[13];
    const float* sa_wv  = (const float*)d_in[15];
    const float* sa_bv  = (const float*)d_in[16];
    float* out = (float*)d_out;

    float *P, *Vn, *P2, *uu, *part;
    __nv_bfloat16 *wv2h, *wv2l, *hbh, *hbl;
    __half *fc16, *wT16, *wv16, *G16, *hn16;
    cudaGetSymbolAddress((void**)&P,    g_P);
    cudaGetSymbolAddress((void**)&Vn,   g_Vn);
    cudaGetSymbolAddress((void**)&P2,   g_P2);
    cudaGetSymbolAddress((void**)&uu,   g_u);
    cudaGetSymbolAddress((void**)&part, g_part);
    cudaGetSymbolAddress((void**)&fc16, g_fc16);
    cudaGetSymbolAddress((void**)&wT16, g_wT16);
    cudaGetSymbolAddress((void**)&wv16, g_wv16);
    cudaGetSymbolAddress((void**)&wv2h, g_wv2_hi);
    cudaGetSymbolAddress((void**)&wv2l, g_wv2_lo);
    cudaGetSymbolAddress((void**)&G16,  g_G16);
    cudaGetSymbolAddress((void**)&hn16, g_hn16);
    cudaGetSymbolAddress((void**)&hbh,  g_hb_hi);
    cudaGetSymbolAddress((void**)&hbl,  g_hb_lo);

    cudaFuncSetAttribute(gemm_mma_b, cudaFuncAttributeMaxDynamicSharedMemorySize, 2 * STAGE_BYTES);
    cudaFuncSetAttribute(gemm_f16,   cudaFuncAttributeMaxDynamicSharedMemorySize, 3 * STAGE16);

    // --- launches 1-3 ---
    split_all16<<<(BB*NN*DD + 2*(int)NW + 255)/256, 256>>>(fc, nsa_wv, sa_wv);
    {
        SplitTSrc st = { { nsa_wq, nsa_wk, sa_wq, sa_wk } };
        splitT_kernel<<<dim3(32, 32, 4), dim3(32, 8)>>>(st);
    }
    u_part<<<dim3(8, 16, 2), 256>>>(nsa_bq, nsa_wk, sa_bq, sa_wk);
    // --- launch 4 (ncu capture slot): Gram GEMMs ---
    {
        Gemm16Batch p = {};
        p.A[0] = wT16 + 1*NW; p.B[0] = wT16 + 0*NW; p.C16[0] = G16;
        p.A[1] = wT16 + 3*NW; p.B[1] = wT16 + 2*NW; p.C16[1] = G16 + NW;
        p.Mstore = DD;
        gemm_f16<<<dim3(16, 16, 2), 128, 3 * STAGE16>>>(p);
    }
    u_reduce<<<dim3(8, 2), 256>>>();

    // z-batched: P = fc16 @ G16^T + u1;  Vn = fc16 @ wv16^T + bv
    {
        Gemm16Batch p = {};
        p.A[0] = fc16; p.B[0] = G16;  p.bias[0] = uu;     p.C[0] = P;
        p.A[1] = fc16; p.B[1] = wv16; p.bias[1] = nsa_bv; p.C[1] = Vn;
        p.Mstore = BB * NN;
        gemm_f16<<<dim3(16, 32, 2), 128, 3 * STAGE16>>>(p);
    }

    attn1_kernel<<<BB, 512>>>(fc);
    coef_kernel<<<dim3(DD / 128, BB), 128>>>(fc, ds_w, ds_b);
    ln_split_kernel<<<BB * WW, 256>>>(ln_g, ln_b);

    // P2 = hn16 @ G2^T + u2
    {
        Gemm16Batch p = {};
        p.A[0] = hn16; p.B[0] = G16 + NW; p.bias[0] = uu + DD; p.C[0] = P2;
        p.Mstore = MPAD2;
        gemm_f16<<<dim3(16, 29, 1), 128, 3 * STAGE16>>>(p);
    }

    dot2_kernel<<<dim3(4, BB), 256>>>();
    cw2_kernel<<<BB, 256>>>();

    // final: out = hbar @ Wv2^T + S[b]*bias (3-product bf16, k-split 8, reduce)
    {
        GemmBatch p = {};
        p.Ah = hbh; p.Al = hbl; p.Bh = wv2h; p.Bl = wv2l; p.C = part;
        p.kSplit = 8;
        gemm_mma_b<<<dim3(16, 1, 8), 128, 2 * STAGE_BYTES>>>(p);
    }
    reduce_final<<<dim3(8, BB), 256>>>(out, sa_bv);
}

// round 15
// speedup vs baseline: 1.1498x; 1.0803x over previous
#include <cuda_runtime.h>
#include <cuda_bf16.h>
#include <cuda_fp16.h>
#include <cstdint>
#include <math.h>

#define BB 64
#define NN 64
#define DD 2048
#define NBW 8
#define WW 57
#define MPAD2 3712
#define SCALE 0.02209708691207961f
#define LNEPS 1e-5f
#define NW ((size_t)DD * DD)

// ============ scratch ============
__device__ float g_P  [BB * NN * DD];
__device__ float g_Vn [BB * NN * DD];
__device__ float g_h  [BB * WW * DD];
__device__ float g_P2 [MPAD2 * DD];
__device__ float g_c  [BB * WW * NBW];
__device__ float g_cw2[BB * WW];
__device__ float g_S  [BB];
__device__ float g_dot2[4 * BB * 64 * 64];
__device__ float g_u  [2 * DD];
__device__ float g_upart[2 * 16 * DD];
__device__ float g_part[8 * 128 * DD];

__device__ __align__(16) __half        g_fc16 [BB * NN * DD];
__device__ __align__(16) __half        g_wT16 [4 * NW];   // WqT, WkT, Wq2T, Wk2T
__device__ __align__(16) __half        g_wv16 [NW];       // Wv (stage 1, fp16)
__device__ __align__(16) __nv_bfloat16 g_wv2_hi[NW];      // Wv2 (final, bf16 hi/lo)
__device__ __align__(16) __nv_bfloat16 g_wv2_lo[NW];
__device__ __align__(16) __half        g_G16  [2 * NW];   // Gram matrices
__device__ __align__(16) __nv_bfloat16 g_hn_hi[MPAD2 * DD];  // rows >=3648 stay zero
__device__ __align__(16) __nv_bfloat16 g_hn_lo[MPAD2 * DD];
__device__ __align__(16) __half        g_hn16 [MPAD2 * DD];
__device__ __align__(16) __nv_bfloat16 g_hb_hi[128 * DD];    // rows >=64 stay zero
__device__ __align__(16) __nv_bfloat16 g_hb_lo[128 * DD];

// ============ merged splits: fc->fp16, Wv->fp16, Wv2->bf16 hi/lo ============
__global__ void split_all16(const float* __restrict__ fc, const float* __restrict__ wv,
                            const float* __restrict__ wv2)
{
    int i = blockIdx.x * 256 + threadIdx.x;
    const int NFC = BB * NN * DD;
    const int NWI = (int)NW;
    if (i < NFC) {
        g_fc16[i] = __float2half(fc[i]);
    } else if (i < NFC + NWI) {
        int j = i - NFC;
        g_wv16[j] = __float2half(wv[j]);
    } else {
        int j = i - NFC - NWI;
        float v = wv2[j];
        __nv_bfloat16 h = __float2bfloat16(v);
        g_wv2_hi[j] = h;
        g_wv2_lo[j] = __float2bfloat16(v - __bfloat162float(h));
    }
}

// transpose to fp16 with coalesced half2 stores: wT16[z][i][m] = W[m][i]
struct SplitTSrc { const float* W[4]; };
__global__ void splitT_kernel(const __grid_constant__ SplitTSrc s)
{
    const int z = blockIdx.z;
    const float* __restrict__ W = s.W[z];
    __half* __restrict__ o = g_wT16 + (size_t)z * NW;
    __shared__ float t[64][65];
    const int m0 = blockIdx.y * 64, i0 = blockIdx.x * 64;
    const int tx = threadIdx.x, ty = threadIdx.y;  // 32, 8
#pragma unroll
    for (int rr = ty; rr < 64; rr += 8) {
        t[rr][tx]      = W[(size_t)(m0 + rr) * DD + i0 + tx];
        t[rr][tx + 32] = W[(size_t)(m0 + rr) * DD + i0 + tx + 32];
    }
    __syncthreads();
#pragma unroll
    for (int ii = ty; ii < 64; ii += 8) {
        __half2 v = __floats2half2_rn(t[tx * 2][ii], t[tx * 2 + 1][ii]);
        *(__half2*)(o + (size_t)(i0 + ii) * DD + m0 + tx * 2) = v;
    }
}

// ============ u[z][j] = sum_m bq[m] * Wk[m][j] ============
__global__ void u_part(const float* __restrict__ b1, const float* __restrict__ W1,
                       const float* __restrict__ b2, const float* __restrict__ W2)
{
    const int z = blockIdx.z;
    const float* __restrict__ b = z ? b2 : b1;
    const float* __restrict__ W = z ? W2 : W1;
    const int j = blockIdx.x * 256 + threadIdx.x;
    const int m0 = blockIdx.y * 128;
    float a = 0.f;
    for (int m = m0; m < m0 + 128; m++) a += b[m] * W[(size_t)m * DD + j];
    g_upart[((size_t)z * 16 + blockIdx.y) * DD + j] = a;
}
__global__ void u_reduce()
{
    const int z = blockIdx.y;
    const int j = blockIdx.x * 256 + threadIdx.x;
    float a = 0.f;
#pragma unroll
    for (int s = 0; s < 16; s++) a += g_upart[((size_t)z * 16 + s) * DD + j];
    g_u[z * DD + j] = a;
}

// ============ common GEMM plumbing ============
#define PITCH 80
__device__ __forceinline__ void cp16(uint32_t saddr, const void* gaddr) {
    asm volatile("cp.async.cg.shared.global [%0], [%1], 16;" :: "r"(saddr), "l"(gaddr));
}
__device__ __forceinline__ uint32_t smem_u32(const void* p) {
    uint32_t a;
    asm("{ .reg .u64 t; cvta.to.shared.u64 t, %1; cvt.u32.u64 %0, t; }" : "=r"(a) : "l"(p));
    return a;
}
#define MMA_BF16(d, a, b) \
    asm volatile("mma.sync.aligned.m16n8k16.row.col.f32.bf16.bf16.f32 " \
        "{%0,%1,%2,%3},{%4,%5,%6,%7},{%8,%9},{%0,%1,%2,%3};" \
        : "+f"((d)[0]), "+f"((d)[1]), "+f"((d)[2]), "+f"((d)[3]) \
        : "r"((a)[0]), "r"((a)[1]), "r"((a)[2]), "r"((a)[3]), "r"((b)[0]), "r"((b)[1]))
#define MMA_F16(d, a, b) \
    asm volatile("mma.sync.aligned.m16n8k16.row.col.f32.f16.f16.f32 " \
        "{%0,%1,%2,%3},{%4,%5,%6,%7},{%8,%9},{%0,%1,%2,%3};" \
        : "+f"((d)[0]), "+f"((d)[1]), "+f"((d)[2]), "+f"((d)[3]) \
        : "r"((a)[0]), "r"((a)[1]), "r"((a)[2]), "r"((a)[3]), "r"((b)[0]), "r"((b)[1]))
#define LDSM_X4(r, addr) \
    asm volatile("ldmatrix.sync.aligned.m8n8.x4.shared.b16 {%0,%1,%2,%3}, [%4];" \
        : "=r"((r)[0]), "=r"((r)[1]), "=r"((r)[2]), "=r"((r)[3]) : "r"(addr))

__device__ __forceinline__ uint32_t a_lane_off(int lane) {
    return (uint32_t)((lane & 15) * PITCH + ((lane >> 4) & 1) * 16);
}
__device__ __forceinline__ uint32_t b_lane_off(int lane) {
    return (uint32_t)(((lane & 7) + ((lane >> 4) & 1) * 8) * PITCH + ((lane >> 3) & 1) * 16);
}

// ============ 3-product bf16 GEMM (final projection only), k-split ============
#define STAGE_BYTES 40960
#define OFF_AH 0
#define OFF_AL 10240
#define OFF_BH 20480
#define OFF_BL 30720

struct GemmBatch {
    const __nv_bfloat16* Ah;
    const __nv_bfloat16* Al;
    const __nv_bfloat16* Bh;
    const __nv_bfloat16* Bl;
    float* C;
    int kSplit;
};

__global__ void __launch_bounds__(128, 2) gemm_mma_b(const __grid_constant__ GemmBatch p)
{
    extern __shared__ char smem[];
    const uint32_t sb = smem_u32(smem);
    const int tid = threadIdx.x;
    const int wid = tid >> 5, lane = tid & 31;
    const int quad = lane >> 2, four = lane & 3;
    const int rowBase = blockIdx.y * 128, colBase = blockIdx.x * 128;
    const int warpM = (wid >> 1) * 64, warpN = (wid & 1) * 64;
    const int slice = blockIdx.z;
    const int chunksPer = (DD / 32) / p.kSplit;
    const int c0 = slice * chunksPer;

    const __nv_bfloat16* __restrict__ Ahi = p.Ah;
    const __nv_bfloat16* __restrict__ Alo = p.Al;
    const __nv_bfloat16* __restrict__ Bhi = p.Bh;
    const __nv_bfloat16* __restrict__ Blo = p.Bl;

    const uint32_t aoff = a_lane_off(lane) + (uint32_t)warpM * PITCH;
    const uint32_t boff = b_lane_off(lane) + (uint32_t)warpN * PITCH;

    float acc[4][8][4];
#pragma unroll
    for (int mi = 0; mi < 4; mi++)
#pragma unroll
        for (int ni = 0; ni < 8; ni++)
#pragma unroll
            for (int r = 0; r < 4; r++) acc[mi][ni][r] = 0.f;

    auto load_stage = [&](int s, int k0) {
        const uint32_t base = sb + (uint32_t)s * STAGE_BYTES;
#pragma unroll
        for (int pp = 0; pp < 4; pp++) {
            int c = tid + pp * 128;
            int row = c >> 2, col = c & 3;
            uint32_t soff = row * PITCH + col * 16;
            size_t ga = (size_t)(rowBase + row) * DD + k0 + col * 8;
            size_t gb = (size_t)(colBase + row) * DD + k0 + col * 8;
            cp16(base + OFF_AH + soff, Ahi + ga);
            cp16(base + OFF_AL + soff, Alo + ga);
            cp16(base + OFF_BH + soff, Bhi + gb);
            cp16(base + OFF_BL + soff, Blo + gb);
        }
        asm volatile("cp.async.commit_group;");
    };

    load_stage(0, c0 * 32);

    for (int cc = 0; cc < chunksPer; cc++) {
        if (cc + 1 < chunksPer) {
            load_stage((cc + 1) & 1, (c0 + cc + 1) * 32);
            asm volatile("cp.async.wait_group 1;");
        } else {
            asm volatile("cp.async.wait_group 0;");
        }
        __syncthreads();

        const uint32_t stg = sb + (uint32_t)(cc & 1) * STAGE_BYTES;
#pragma unroll
        for (int kk = 0; kk < 2; kk++) {
            const uint32_t kb = kk * 32;
            uint32_t ah[4][4], al[4][4], bhq[4][4], blq[4][4];
#pragma unroll
            for (int mi = 0; mi < 4; mi++) {
                uint32_t ad = stg + aoff + (uint32_t)(mi * 16) * PITCH + kb;
                LDSM_X4(ah[mi], ad + OFF_AH);
                LDSM_X4(al[mi], ad + OFF_AL);
            }
#pragma unroll
            for (int np = 0; np < 4; np++) {
                uint32_t bd = stg + boff + (uint32_t)(np * 16) * PITCH + kb;
                LDSM_X4(bhq[np], bd + OFF_BH);
                LDSM_X4(blq[np], bd + OFF_BL);
            }
#pragma unroll
            for (int mi = 0; mi < 4; mi++)
#pragma unroll
                for (int ni = 0; ni < 8; ni++)
                    MMA_BF16(acc[mi][ni], ah[mi], (&bhq[ni >> 1][(ni & 1) * 2]));
#pragma unroll
            for (int mi = 0; mi < 4; mi++)
#pragma unroll
                for (int ni = 0; ni < 8; ni++)
                    MMA_BF16(acc[mi][ni], ah[mi], (&blq[ni >> 1][(ni & 1) * 2]));
#pragma unroll
            for (int mi = 0; mi < 4; mi++)
#pragma unroll
                for (int ni = 0; ni < 8; ni++)
                    MMA_BF16(acc[mi][ni], al[mi], (&bhq[ni >> 1][(ni & 1) * 2]));
        }
        __syncthreads();
    }

    float* __restrict__ Cp = p.C + (size_t)slice * (gridDim.y * 128) * DD;
#pragma unroll
    for (int mi = 0; mi < 4; mi++) {
        int gr0 = rowBase + warpM + mi * 16 + quad;
        int gr1 = gr0 + 8;
#pragma unroll
        for (int ni = 0; ni < 8; ni++) {
            int gc = colBase + warpN + ni * 8 + four * 2;
            *(float2*)&Cp[(size_t)gr0 * DD + gc] = make_float2(acc[mi][ni][0], acc[mi][ni][1]);
            *(float2*)&Cp[(size_t)gr1 * DD + gc] = make_float2(acc[mi][ni][2], acc[mi][ni][3]);
        }
    }
}

// ============ single-product fp16 GEMM, 128 threads, k-chunk 32, 3-stage ============
#define STAGE16 20480
#define OFF_B16 10240

struct Gemm16Batch {
    const __half* A[2];
    const __half* B[2];
    const float* bias[2];
    float* C[2];
    __half* C16[2];
    int Mstore;
};

__global__ void __launch_bounds__(128, 2) gemm_f16(const __grid_constant__ Gemm16Batch p)
{
    extern __shared__ char smem[];
    const uint32_t sb = smem_u32(smem);
    const int tid = threadIdx.x;
    const int wid = tid >> 5, lane = tid & 31;
    const int quad = lane >> 2, four = lane & 3;
    const int rowBase = blockIdx.y * 128, colBase = blockIdx.x * 128;
    const int warpM = (wid >> 1) * 64, warpN = (wid & 1) * 64;
    const int z = blockIdx.z;

    const __half* __restrict__ A = p.A[z];
    const __half* __restrict__ B = p.B[z];

    const uint32_t aoff = a_lane_off(lane) + (uint32_t)warpM * PITCH;
    const uint32_t boff = b_lane_off(lane) + (uint32_t)warpN * PITCH + OFF_B16;

    float acc[4][8][4];
#pragma unroll
    for (int mi = 0; mi < 4; mi++)
#pragma unroll
        for (int ni = 0; ni < 8; ni++)
#pragma unroll
            for (int r = 0; r < 4; r++) acc[mi][ni][r] = 0.f;

    auto load_stage = [&](int s, int k0) {
        const uint32_t base = sb + (uint32_t)s * STAGE16;
#pragma unroll
        for (int pp = 0; pp < 4; pp++) {
            int c = tid + pp * 128;
            int row = c >> 2, col = c & 3;
            uint32_t soff = row * PITCH + col * 16;
            cp16(base + soff,            A + (size_t)(rowBase + row) * DD + k0 + col * 8);
            cp16(base + OFF_B16 + soff,  B + (size_t)(colBase + row) * DD + k0 + col * 8);
        }
        asm volatile("cp.async.commit_group;");
    };

    load_stage(0, 0);
    load_stage(1, 32);

    const int NCHUNK = DD / 32;
    int stageIdx = 0;
    for (int cc = 0; cc < NCHUNK; cc++) {
        if (cc + 2 < NCHUNK) {
            int s2 = stageIdx + 2; if (s2 >= 3) s2 -= 3;
            load_stage(s2, (cc + 2) * 32);
            asm volatile("cp.async.wait_group 2;");
        } else if (cc + 1 < NCHUNK) {
            asm volatile("cp.async.wait_group 1;");
        } else {
            asm volatile("cp.async.wait_group 0;");
        }
        __syncthreads();

        const uint32_t stg = sb + (uint32_t)stageIdx * STAGE16;
#pragma unroll
        for (int kk = 0; kk < 2; kk++) {
            const uint32_t kb = kk * 32;
            uint32_t ah[4][4], bq[4][4];
#pragma unroll
            for (int mi = 0; mi < 4; mi++)
                LDSM_X4(ah[mi], stg + aoff + (uint32_t)(mi * 16) * PITCH + kb);
#pragma unroll
            for (int np = 0; np < 4; np++)
                LDSM_X4(bq[np], stg + boff + (uint32_t)(np * 16) * PITCH + kb);
#pragma unroll
            for (int mi = 0; mi < 4; mi++)
#pragma unroll
                for (int ni = 0; ni < 8; ni++)
                    MMA_F16(acc[mi][ni], ah[mi], (&bq[ni >> 1][(ni & 1) * 2]));
        }
        __syncthreads();
        if (++stageIdx == 3) stageIdx = 0;
    }

    const int Mstore = p.Mstore;
    if (p.C16[z]) {
        __half* __restrict__ O = p.C16[z];
#pragma unroll
        for (int mi = 0; mi < 4; mi++) {
            int gr0 = rowBase + warpM + mi * 16 + quad;
            int gr1 = gr0 + 8;
#pragma unroll
            for (int ni = 0; ni < 8; ni++) {
                int gc = colBase + warpN + ni * 8 + four * 2;
                *(__half2*)&O[(size_t)gr0 * DD + gc] =
                    __floats2half2_rn(acc[mi][ni][0], acc[mi][ni][1]);
                *(__half2*)&O[(size_t)gr1 * DD + gc] =
                    __floats2half2_rn(acc[mi][ni][2], acc[mi][ni][3]);
            }
        }
    } else {
        const float* __restrict__ bias = p.bias[z];
        float* __restrict__ C = p.C[z];
#pragma unroll
        for (int mi = 0; mi < 4; mi++) {
            int gr0 = rowBase + warpM + mi * 16 + quad;
            int gr1 = gr0 + 8;
#pragma unroll
            for (int ni = 0; ni < 8; ni++) {
                int gc = colBase + warpN + ni * 8 + four * 2;
                float b0 = bias[gc], b1 = bias[gc + 1];
                if (gr0 < Mstore)
                    *(float2*)&C[(size_t)gr0 * DD + gc] =
                        make_float2(acc[mi][ni][0] + b0, acc[mi][ni][1] + b1);
                if (gr1 < Mstore)
                    *(float2*)&C[(size_t)gr1 * DD + gc] =
                        make_float2(acc[mi][ni][2] + b0, acc[mi][ni][3] + b1);
            }
        }
    }
}

// ============ final reduce ============
__global__ void reduce_final(float* __restrict__ out, const float* __restrict__ bias)
{
    const int r = blockIdx.y;
    const int c = blockIdx.x * 256 + threadIdx.x;
    float a = 0.f;
#pragma unroll
    for (int s = 0; s < 8; s++) a += g_part[(size_t)s * 128 * DD + (size_t)r * DD + c];
    out[(size_t)r * DD + c] = a + bias[c] * g_S[r];
}

// ============ stage-1 window attention: banded dots of P vs fc ============
__global__ void __launch_bounds__(512) attn1_kernel(const float* __restrict__ fc)
{
    const int b = blockIdx.x;
    const int tid = threadIdx.x;
    const int warp = tid >> 5, lane = tid & 31;
    const int r0 = warp * 4;

    __shared__ float Qc[64][65];
    __shared__ float Kc[64][65];
    __shared__ float band[64][15];

    float acc[60];
#pragma unroll
    for (int e = 0; e < 60; e++) acc[e] = 0.f;

    for (int ch = 0; ch < 32; ch++) {
#pragma unroll
        for (int pp = 0; pp < 2; pp++) {
            int f4 = tid + pp * 512;
            int row = f4 >> 4, q = f4 & 15;
            const float4 v = *(const float4*)(g_P + ((size_t)b * NN + row) * DD + ch * 64 + q * 4);
            const float4 u = *(const float4*)(fc  + ((size_t)b * NN + row) * DD + ch * 64 + q * 4);
            Qc[row][q*4+0] = v.x; Qc[row][q*4+1] = v.y; Qc[row][q*4+2] = v.z; Qc[row][q*4+3] = v.w;
            Kc[row][q*4+0] = u.x; Kc[row][q*4+1] = u.y; Kc[row][q*4+2] = u.z; Kc[row][q*4+3] = u.w;
        }
        __syncthreads();
#pragma unroll
        for (int t = 0; t < 2; t++) {
            int dd = lane + t * 32;
            float qv[4];
#pragma unroll
            for (int i = 0; i < 4; i++) qv[i] = Qc[r0 + i][dd];
            float kv[18];
#pragma unroll
            for (int jj = 0; jj < 18; jj++) {
                int cc = r0 - 7 + jj;
                kv[jj] = (cc >= 0 && cc < 64) ? Kc[cc][dd] : 0.f;
            }
#pragma unroll
            for (int i = 0; i < 4; i++)
#pragma unroll
                for (int d5 = 0; d5 < 15; d5++)
                    acc[i * 15 + d5] += qv[i] * kv[i + d5];
        }
        __syncthreads();
    }
#pragma unroll
    for (int e = 0; e < 60; e++) {
#pragma unroll
        for (int off = 16; off; off >>= 1)
            acc[e] += __shfl_xor_sync(0xFFFFFFFFu, acc[e], off);
    }
    if (lane == 0) {
#pragma unroll
        for (int i = 0; i < 4; i++)
#pragma unroll
            for (int d5 = 0; d5 < 15; d5++) {
                int r = r0 + i, cc = r + d5 - 7;
                if (cc >= 0 && cc < 64) band[r][d5] = acc[i * 15 + d5];
            }
    }
    __syncthreads();

    if (tid < WW) {
        int w = tid;
        float col[8];
#pragma unroll
        for (int j = 0; j < 8; j++) col[j] = 0.f;
#pragma unroll
        for (int i = 0; i < 8; i++) {
            float s[8], m = -1e30f;
#pragma unroll
            for (int j = 0; j < 8; j++) {
                s[j] = band[w + i][j - i + 7] * SCALE;
                m = fmaxf(m, s[j]);
            }
            float e[8], sum = 0.f;
#pragma unroll
            for (int j = 0; j < 8; j++) { e[j] = __expf(s[j] - m); sum += e[j]; }
            float inv = 1.f / sum;
#pragma unroll
            for (int j = 0; j < 8; j++) col[j] += e[j] * inv;
        }
#pragma unroll
        for (int j = 0; j < 8; j++)
            g_c[((size_t)b * WW + w) * NBW + j] = col[j];
    }
}

// ============ h = downsample + nsa ============
__global__ void coef_kernel(const float* __restrict__ fc, const float* __restrict__ ds_w,
                            const float* __restrict__ ds_b)
{
    const int b = blockIdx.y;
    const int d = blockIdx.x * 128 + threadIdx.x;

    __shared__ float sA[WW * NN];
    __shared__ float sB[WW * NN];
    for (int i = threadIdx.x; i < WW * NN; i += 128) { sA[i] = ds_w[i]; sB[i] = 0.f; }
    __syncthreads();
    for (int i = threadIdx.x; i < WW * NBW; i += 128) {
        int w = i / NBW, j = i % NBW;
        sB[w * NN + w + j] = g_c[((size_t)b * WW + w) * NBW + j];
    }
    __syncthreads();

    const float* fcb = fc + (size_t)b * NN * DD + d;
    const float* vnb = g_Vn + (size_t)b * NN * DD + d;

    float acc[WW];
#pragma unroll
    for (int w = 0; w < WW; w++) acc[w] = 0.f;
    for (int n = 0; n < NN; n++) {
        float fv = fcb[(size_t)n * DD];
        float vv = vnb[(size_t)n * DD];
#pragma unroll
        for (int w = 0; w < WW; w++)
            acc[w] += fv * sA[w * NN + n] + vv * sB[w * NN + n];
    }
    float* hb = g_h + (size_t)b * WW * DD + d;
#pragma unroll
    for (int w = 0; w < WW; w++)
        hb[(size_t)w * DD] = acc[w] + ds_b[w];
}

// ============ LayerNorm -> bf16 hi/lo + fp16 ============
__global__ void ln_split_kernel(const float* __restrict__ g, const float* __restrict__ beta)
{
    const int row = blockIdx.x;
    const int tid = threadIdx.x;
    const float* hr = g_h + (size_t)row * DD;

    float v[8], s = 0.f, s2 = 0.f;
#pragma unroll
    for (int p = 0; p < 8; p++) {
        v[p] = hr[tid + p * 256];
        s += v[p]; s2 += v[p] * v[p];
    }
#pragma unroll
    for (int off = 16; off; off >>= 1) {
        s  += __shfl_xor_sync(0xFFFFFFFFu, s, off);
        s2 += __shfl_xor_sync(0xFFFFFFFFu, s2, off);
    }
    __shared__ float ws[8], ws2[8], smu, sinv;
    const int warp = tid >> 5, lane = tid & 31;
    if (lane == 0) { ws[warp] = s; ws2[warp] = s2; }
    __syncthreads();
    if (warp == 0) {
        float a  = (lane < 8) ? ws[lane]  : 0.f;
        float a2 = (lane < 8) ? ws2[lane] : 0.f;
#pragma unroll
        for (int off = 4; off; off >>= 1) {
            a  += __shfl_xor_sync(0xFFFFFFFFu, a, off);
            a2 += __shfl_xor_sync(0xFFFFFFFFu, a2, off);
        }
        if (lane == 0) {
            float mu = a / (float)DD;
            smu = mu; sinv = rsqrtf(a2 / (float)DD - mu * mu + LNEPS);
        }
    }
    __syncthreads();
    float mu = smu, inv = sinv;
#pragma unroll
    for (int p = 0; p < 8; p++) {
        int d = tid + p * 256;
        float y = (v[p] - mu) * inv * g[d] + beta[d];
        __nv_bfloat16 h = __float2bfloat16(y);
        g_hn_hi[(size_t)row * DD + d] = h;
        g_hn_lo[(size_t)row * DD + d] = __float2bfloat16(y - __bfloat162float(h));
        g_hn16[(size_t)row * DD + d]  = __float2half(y);
    }
}

// ============ stage-2 scores: P2 vs hn16, K-split 64x64 ============
__global__ void dot2_kernel()
{
    const int sl = blockIdx.x, b = blockIdx.y;
    const int tid = threadIdx.x;
    const int ty = tid >> 4, tx = tid & 15;

    __shared__ float Qc[64][33];
    __shared__ float Kc[64][33];

    float acc[4][4];
#pragma unroll
    for (int i = 0; i < 4; i++)
#pragma unroll
        for (int j = 0; j < 4; j++) acc[i][j] = 0.f;

    const size_t rb = (size_t)b * WW;
    for (int ch = 0; ch < 16; ch++) {
        int k0 = sl * 512 + ch * 32;
#pragma unroll
        for (int pq = 0; pq < 2; pq++) {
            int idx = tid + pq * 256;
            int row = idx >> 3, q = idx & 7;
            float4 v = *(const float4*)(g_P2 + (rb + row) * DD + k0 + q * 4);
            Qc[row][q*4+0] = v.x; Qc[row][q*4+1] = v.y; Qc[row][q*4+2] = v.z; Qc[row][q*4+3] = v.w;
        }
        {
            int row = tid >> 2, q = tid & 3;
            const uint4 hv = *(const uint4*)(g_hn16 + (rb + row) * DD + k0 + q * 8);
            const __half* hp = (const __half*)&hv;
#pragma unroll
            for (int e = 0; e < 8; e++)
                Kc[row][q*8+e] = __half2float(hp[e]);
        }
        __syncthreads();
#pragma unroll
        for (int d = 0; d < 32; d++) {
            float ra[4], rv[4];
#pragma unroll
            for (int i = 0; i < 4; i++) ra[i] = Qc[ty * 4 + i][d];
#pragma unroll
            for (int j = 0; j < 4; j++) rv[j] = Kc[tx * 4 + j][d];
#pragma unroll
            for (int i = 0; i < 4; i++)
#pragma unroll
                for (int j = 0; j < 4; j++) acc[i][j] += ra[i] * rv[j];
        }
        __syncthreads();
    }
#pragma unroll
    for (int i = 0; i < 4; i++)
#pragma unroll
        for (int j = 0; j < 4; j++)
            g_dot2[(((size_t)sl * BB + b) * 64 + ty * 4 + i) * 64 + tx * 4 + j] = acc[i][j];
}

// ============ stage-2 softmax column sums ============
__global__ void cw2_kernel()
{
    const int b = blockIdx.x;
    const int tid = threadIdx.x;
    __shared__ float s[WW * 64];
    __shared__ float rmax[WW], rinv[WW], cs[WW];

    for (int idx = tid; idx < WW * 64; idx += 256) {
        int i = idx >> 6, j = idx & 63;
        float v = 0.f;
        if (j < WW) {
#pragma unroll
            for (int sl = 0; sl < 4; sl++)
                v += g_dot2[(((size_t)sl * BB + b) * 64 + i) * 64 + j];
        }
        s[idx] = v * SCALE;
    }
    __syncthreads();
    if (tid < WW) {
        float m = -1e30f;
        for (int j = 0; j < WW; j++) m = fmaxf(m, s[tid * 64 + j]);
        float sum = 0.f;
        for (int j = 0; j < WW; j++) sum += __expf(s[tid * 64 + j] - m);
        rmax[tid] = m; rinv[tid] = 1.f / sum;
    }
    __syncthreads();
    if (tid < WW) {
        float col = 0.f;
        for (int i = 0; i < WW; i++)
            col += __expf(s[i * 64 + tid] - rmax[i]) * rinv[i];
        cs[tid] = col;
        g_cw2[(size_t)b * WW + tid] = col;
    }
    __syncthreads();
    if (tid == 0) {
        float t = 0.f;
        for (int j = 0; j < WW; j++) t += cs[j];
        g_S[b] = t;
    }
}

// ============ hbar -> bf16 hi/lo ============
__global__ void hbar_kernel()
{
    const int b = blockIdx.y;
    const int d = blockIdx.x * 256 + threadIdx.x;

    __shared__ float sc[WW];
    if (threadIdx.x < WW) sc[threadIdx.x] = g_cw2[(size_t)b * WW + threadIdx.x];
    __syncthreads();

    float a = 0.f;
#pragma unroll
    for (int j = 0; j < WW; j++) {
        size_t r = (size_t)(b * WW + j) * DD + d;
        a += sc[j] * (__bfloat162float(g_hn_hi[r]) + __bfloat162float(g_hn_lo[r]));
    }
    __nv_bfloat16 h = __float2bfloat16(a);
    g_hb_hi[(size_t)b * DD + d] = h;
    g_hb_lo[(size_t)b * DD + d] = __float2bfloat16(a - __bfloat162float(h));
}

// ============ launch ============
extern "C" void kernel_launch(void* const* d_in, const int* in_sizes, int n_in,
                              void* d_out, int out_size)
{
    (void)in_sizes; (void)n_in; (void)out_size;

    const float* fc     = (const float*)d_in[0];
    const float* nsa_wq = (const float*)d_in[1];
    const float* nsa_bq = (const float*)d_in[2];
    const float* nsa_wk = (const float*)d_in[3];
    const float* nsa_wv = (const float*)d_in[5];
    const float* nsa_bv = (const float*)d_in[6];
    const float* ds_w   = (const float*)d_in[7];
    const float* ds_b   = (const float*)d_in[8];
    const float* ln_g   = (const float*)d_in[9];
    const float* ln_b   = (const float*)d_in[10];
    const float* sa_wq  = (const float*)d_in[11];
    const float* sa_bq  = (const float*)d_in[12];
    const float* sa_wk  = (const float*)d_in[13];
    const float* sa_wv  = (const float*)d_in[15];
    const float* sa_bv  = (const float*)d_in[16];
    float* out = (float*)d_out;

    float *P, *Vn, *P2, *uu, *part;
    __nv_bfloat16 *wv2h, *wv2l, *hbh, *hbl;
    __half *fc16, *wT16, *wv16, *G16, *hn16;
    cudaGetSymbolAddress((void**)&P,    g_P);
    cudaGetSymbolAddress((void**)&Vn,   g_Vn);
    cudaGetSymbolAddress((void**)&P2,   g_P2);
    cudaGetSymbolAddress((void**)&uu,   g_u);
    cudaGetSymbolAddress((void**)&part, g_part);
    cudaGetSymbolAddress((void**)&fc16, g_fc16);
    cudaGetSymbolAddress((void**)&wT16, g_wT16);
    cudaGetSymbolAddress((void**)&wv16, g_wv16);
    cudaGetSymbolAddress((void**)&wv2h, g_wv2_hi);
    cudaGetSymbolAddress((void**)&wv2l, g_wv2_lo);
    cudaGetSymbolAddress((void**)&G16,  g_G16);
    cudaGetSymbolAddress((void**)&hn16, g_hn16);
    cudaGetSymbolAddress((void**)&hbh,  g_hb_hi);
    cudaGetSymbolAddress((void**)&hbl,  g_hb_lo);

    cudaFuncSetAttribute(gemm_mma_b, cudaFuncAttributeMaxDynamicSharedMemorySize, 2 * STAGE_BYTES);
    cudaFuncSetAttribute(gemm_f16,   cudaFuncAttributeMaxDynamicSharedMemorySize, 3 * STAGE16);

    // --- launches 1-3 ---
    split_all16<<<(BB*NN*DD + 2*(int)NW + 255)/256, 256>>>(fc, nsa_wv, sa_wv);
    {
        SplitTSrc st = { { nsa_wq, nsa_wk, sa_wq, sa_wk } };
        splitT_kernel<<<dim3(32, 32, 4), dim3(32, 8)>>>(st);
    }
    u_part<<<dim3(8, 16, 2), 256>>>(nsa_bq, nsa_wk, sa_bq, sa_wk);
    // --- launch 4 (ncu capture slot): Gram GEMMs ---
    {
        Gemm16Batch p = {};
        p.A[0] = wT16 + 1*NW; p.B[0] = wT16 + 0*NW; p.C16[0] = G16;
        p.A[1] = wT16 + 3*NW; p.B[1] = wT16 + 2*NW; p.C16[1] = G16 + NW;
        p.Mstore = DD;
        gemm_f16<<<dim3(16, 16, 2), 128, 3 * STAGE16>>>(p);
    }
    u_reduce<<<dim3(8, 2), 256>>>();

    // z-batched: P = fc16 @ G16^T + u1;  Vn = fc16 @ wv16^T + bv
    {
        Gemm16Batch p = {};
        p.A[0] = fc16; p.B[0] = G16;  p.bias[0] = uu;     p.C[0] = P;
        p.A[1] = fc16; p.B[1] = wv16; p.bias[1] = nsa_bv; p.C[1] = Vn;
        p.Mstore = BB * NN;
        gemm_f16<<<dim3(16, 32, 2), 128, 3 * STAGE16>>>(p);
    }

    attn1_kernel<<<BB, 512>>>(fc);
    coef_kernel<<<dim3(DD / 128, BB), 128>>>(fc, ds_w, ds_b);
    ln_split_kernel<<<BB * WW, 256>>>(ln_g, ln_b);

    // P2 = hn16 @ G2^T + u2
    {
        Gemm16Batch p = {};
        p.A[0] = hn16; p.B[0] = G16 + NW; p.bias[0] = uu + DD; p.C[0] = P2;
        p.Mstore = MPAD2;
        gemm_f16<<<dim3(16, 29, 1), 128, 3 * STAGE16>>>(p);
    }

    dot2_kernel<<<dim3(4, BB), 256>>>();
    cw2_kernel<<<BB, 256>>>();
    hbar_kernel<<<dim3(DD / 256, BB), 256>>>();

    // final: out = hbar @ Wv2^T + S[b]*bias (3-product bf16, k-split 8, reduce)
    {
        GemmBatch p = {};
        p.Ah = hbh; p.Al = hbl; p.Bh = wv2h; p.Bl = wv2l; p.C = part;
        p.kSplit = 8;
        gemm_mma_b<<<dim3(16, 1, 8), 128, 2 * STAGE_BYTES>>>(p);
    }
    reduce_final<<<dim3(8, BB), 256>>>(out, sa_bv);
}

// round 16
// speedup vs baseline: 1.1774x; 1.0239x over previous
#include <cuda_runtime.h>
#include <cuda_bf16.h>
#include <cuda_fp16.h>
#include <cstdint>
#include <math.h>

#define BB 64
#define NN 64
#define DD 2048
#define NBW 8
#define WW 57
#define MPAD2 3712
#define SCALE 0.02209708691207961f
#define LNEPS 1e-5f
#define NW ((size_t)DD * DD)

// ============ scratch ============
__device__ float g_P  [BB * NN * DD];
__device__ float g_Vn [BB * NN * DD];
__device__ float g_h  [BB * WW * DD];
__device__ float g_P2 [MPAD2 * DD];
__device__ float g_c  [BB * WW * NBW];
__device__ float g_cw2[BB * WW];
__device__ float g_S  [BB];
__device__ float g_dot2[4 * BB * 64 * 64];
__device__ float g_band[4 * BB * 64 * 15];
__device__ float g_u  [2 * DD];
__device__ float g_upart[2 * 16 * DD];
__device__ float g_part[8 * 128 * DD];

__device__ __align__(16) __half        g_fc16 [BB * NN * DD];
__device__ __align__(16) __half        g_wT16 [4 * NW];   // WqT, WkT, Wq2T, Wk2T
__device__ __align__(16) __half        g_wv16 [NW];       // Wv (stage 1, fp16)
__device__ __align__(16) __nv_bfloat16 g_wv2_hi[NW];      // Wv2 (final, bf16 hi/lo)
__device__ __align__(16) __nv_bfloat16 g_wv2_lo[NW];
__device__ __align__(16) __half        g_G16  [2 * NW];   // Gram matrices
__device__ __align__(16) __nv_bfloat16 g_hn_hi[MPAD2 * DD];  // rows >=3648 stay zero
__device__ __align__(16) __nv_bfloat16 g_hn_lo[MPAD2 * DD];
__device__ __align__(16) __half        g_hn16 [MPAD2 * DD];
__device__ __align__(16) __nv_bfloat16 g_hb_hi[128 * DD];    // rows >=64 stay zero
__device__ __align__(16) __nv_bfloat16 g_hb_lo[128 * DD];

// ============ merged splits: fc->fp16, Wv->fp16, Wv2->bf16 hi/lo ============
__global__ void split_all16(const float* __restrict__ fc, const float* __restrict__ wv,
                            const float* __restrict__ wv2)
{
    int i = blockIdx.x * 256 + threadIdx.x;
    const int NFC = BB * NN * DD;
    const int NWI = (int)NW;
    if (i < NFC) {
        g_fc16[i] = __float2half(fc[i]);
    } else if (i < NFC + NWI) {
        int j = i - NFC;
        g_wv16[j] = __float2half(wv[j]);
    } else {
        int j = i - NFC - NWI;
        float v = wv2[j];
        __nv_bfloat16 h = __float2bfloat16(v);
        g_wv2_hi[j] = h;
        g_wv2_lo[j] = __float2bfloat16(v - __bfloat162float(h));
    }
}

// transpose to fp16 with coalesced half2 stores: wT16[z][i][m] = W[m][i]
struct SplitTSrc { const float* W[4]; };
__global__ void splitT_kernel(const __grid_constant__ SplitTSrc s)
{
    const int z = blockIdx.z;
    const float* __restrict__ W = s.W[z];
    __half* __restrict__ o = g_wT16 + (size_t)z * NW;
    __shared__ float t[64][65];
    const int m0 = blockIdx.y * 64, i0 = blockIdx.x * 64;
    const int tx = threadIdx.x, ty = threadIdx.y;  // 32, 8
#pragma unroll
    for (int rr = ty; rr < 64; rr += 8) {
        t[rr][tx]      = W[(size_t)(m0 + rr) * DD + i0 + tx];
        t[rr][tx + 32] = W[(size_t)(m0 + rr) * DD + i0 + tx + 32];
    }
    __syncthreads();
#pragma unroll
    for (int ii = ty; ii < 64; ii += 8) {
        __half2 v = __floats2half2_rn(t[tx * 2][ii], t[tx * 2 + 1][ii]);
        *(__half2*)(o + (size_t)(i0 + ii) * DD + m0 + tx * 2) = v;
    }
}

// ============ u[z][j] = sum_m bq[m] * Wk[m][j] ============
__global__ void u_part(const float* __restrict__ b1, const float* __restrict__ W1,
                       const float* __restrict__ b2, const float* __restrict__ W2)
{
    const int z = blockIdx.z;
    const float* __restrict__ b = z ? b2 : b1;
    const float* __restrict__ W = z ? W2 : W1;
    const int j = blockIdx.x * 256 + threadIdx.x;
    const int m0 = blockIdx.y * 128;
    float a = 0.f;
    for (int m = m0; m < m0 + 128; m++) a += b[m] * W[(size_t)m * DD + j];
    g_upart[((size_t)z * 16 + blockIdx.y) * DD + j] = a;
}
__global__ void u_reduce()
{
    const int z = blockIdx.y;
    const int j = blockIdx.x * 256 + threadIdx.x;
    float a = 0.f;
#pragma unroll
    for (int s = 0; s < 16; s++) a += g_upart[((size_t)z * 16 + s) * DD + j];
    g_u[z * DD + j] = a;
}

// ============ common GEMM plumbing ============
#define PITCH 80
__device__ __forceinline__ void cp16(uint32_t saddr, const void* gaddr) {
    asm volatile("cp.async.cg.shared.global [%0], [%1], 16;" :: "r"(saddr), "l"(gaddr));
}
__device__ __forceinline__ uint32_t smem_u32(const void* p) {
    uint32_t a;
    asm("{ .reg .u64 t; cvta.to.shared.u64 t, %1; cvt.u32.u64 %0, t; }" : "=r"(a) : "l"(p));
    return a;
}
#define MMA_BF16(d, a, b) \
    asm volatile("mma.sync.aligned.m16n8k16.row.col.f32.bf16.bf16.f32 " \
        "{%0,%1,%2,%3},{%4,%5,%6,%7},{%8,%9},{%0,%1,%2,%3};" \
        : "+f"((d)[0]), "+f"((d)[1]), "+f"((d)[2]), "+f"((d)[3]) \
        : "r"((a)[0]), "r"((a)[1]), "r"((a)[2]), "r"((a)[3]), "r"((b)[0]), "r"((b)[1]))
#define MMA_F16(d, a, b) \
    asm volatile("mma.sync.aligned.m16n8k16.row.col.f32.f16.f16.f32 " \
        "{%0,%1,%2,%3},{%4,%5,%6,%7},{%8,%9},{%0,%1,%2,%3};" \
        : "+f"((d)[0]), "+f"((d)[1]), "+f"((d)[2]), "+f"((d)[3]) \
        : "r"((a)[0]), "r"((a)[1]), "r"((a)[2]), "r"((a)[3]), "r"((b)[0]), "r"((b)[1]))
#define LDSM_X4(r, addr) \
    asm volatile("ldmatrix.sync.aligned.m8n8.x4.shared.b16 {%0,%1,%2,%3}, [%4];" \
        : "=r"((r)[0]), "=r"((r)[1]), "=r"((r)[2]), "=r"((r)[3]) : "r"(addr))

__device__ __forceinline__ uint32_t a_lane_off(int lane) {
    return (uint32_t)((lane & 15) * PITCH + ((lane >> 4) & 1) * 16);
}
__device__ __forceinline__ uint32_t b_lane_off(int lane) {
    return (uint32_t)(((lane & 7) + ((lane >> 4) & 1) * 8) * PITCH + ((lane >> 3) & 1) * 16);
}

// ============ 3-product bf16 GEMM (final projection only), k-split ============
#define STAGE_BYTES 40960
#define OFF_AH 0
#define OFF_AL 10240
#define OFF_BH 20480
#define OFF_BL 30720

struct GemmBatch {
    const __nv_bfloat16* Ah;
    const __nv_bfloat16* Al;
    const __nv_bfloat16* Bh;
    const __nv_bfloat16* Bl;
    float* C;
    int kSplit;
};

__global__ void __launch_bounds__(128, 2) gemm_mma_b(const __grid_constant__ GemmBatch p)
{
    extern __shared__ char smem[];
    const uint32_t sb = smem_u32(smem);
    const int tid = threadIdx.x;
    const int wid = tid >> 5, lane = tid & 31;
    const int quad = lane >> 2, four = lane & 3;
    const int rowBase = blockIdx.y * 128, colBase = blockIdx.x * 128;
    const int warpM = (wid >> 1) * 64, warpN = (wid & 1) * 64;
    const int slice = blockIdx.z;
    const int chunksPer = (DD / 32) / p.kSplit;
    const int c0 = slice * chunksPer;

    const __nv_bfloat16* __restrict__ Ahi = p.Ah;
    const __nv_bfloat16* __restrict__ Alo = p.Al;
    const __nv_bfloat16* __restrict__ Bhi = p.Bh;
    const __nv_bfloat16* __restrict__ Blo = p.Bl;

    const uint32_t aoff = a_lane_off(lane) + (uint32_t)warpM * PITCH;
    const uint32_t boff = b_lane_off(lane) + (uint32_t)warpN * PITCH;

    float acc[4][8][4];
#pragma unroll
    for (int mi = 0; mi < 4; mi++)
#pragma unroll
        for (int ni = 0; ni < 8; ni++)
#pragma unroll
            for (int r = 0; r < 4; r++) acc[mi][ni][r] = 0.f;

    auto load_stage = [&](int s, int k0) {
        const uint32_t base = sb + (uint32_t)s * STAGE_BYTES;
#pragma unroll
        for (int pp = 0; pp < 4; pp++) {
            int c = tid + pp * 128;
            int row = c >> 2, col = c & 3;
            uint32_t soff = row * PITCH + col * 16;
            size_t ga = (size_t)(rowBase + row) * DD + k0 + col * 8;
            size_t gb = (size_t)(colBase + row) * DD + k0 + col * 8;
            cp16(base + OFF_AH + soff, Ahi + ga);
            cp16(base + OFF_AL + soff, Alo + ga);
            cp16(base + OFF_BH + soff, Bhi + gb);
            cp16(base + OFF_BL + soff, Blo + gb);
        }
        asm volatile("cp.async.commit_group;");
    };

    load_stage(0, c0 * 32);

    for (int cc = 0; cc < chunksPer; cc++) {
        if (cc + 1 < chunksPer) {
            load_stage((cc + 1) & 1, (c0 + cc + 1) * 32);
            asm volatile("cp.async.wait_group 1;");
        } else {
            asm volatile("cp.async.wait_group 0;");
        }
        __syncthreads();

        const uint32_t stg = sb + (uint32_t)(cc & 1) * STAGE_BYTES;
#pragma unroll
        for (int kk = 0; kk < 2; kk++) {
            const uint32_t kb = kk * 32;
            uint32_t ah[4][4], al[4][4], bhq[4][4], blq[4][4];
#pragma unroll
            for (int mi = 0; mi < 4; mi++) {
                uint32_t ad = stg + aoff + (uint32_t)(mi * 16) * PITCH + kb;
                LDSM_X4(ah[mi], ad + OFF_AH);
                LDSM_X4(al[mi], ad + OFF_AL);
            }
#pragma unroll
            for (int np = 0; np < 4; np++) {
                uint32_t bd = stg + boff + (uint32_t)(np * 16) * PITCH + kb;
                LDSM_X4(bhq[np], bd + OFF_BH);
                LDSM_X4(blq[np], bd + OFF_BL);
            }
#pragma unroll
            for (int mi = 0; mi < 4; mi++)
#pragma unroll
                for (int ni = 0; ni < 8; ni++)
                    MMA_BF16(acc[mi][ni], ah[mi], (&bhq[ni >> 1][(ni & 1) * 2]));
#pragma unroll
            for (int mi = 0; mi < 4; mi++)
#pragma unroll
                for (int ni = 0; ni < 8; ni++)
                    MMA_BF16(acc[mi][ni], ah[mi], (&blq[ni >> 1][(ni & 1) * 2]));
#pragma unroll
            for (int mi = 0; mi < 4; mi++)
#pragma unroll
                for (int ni = 0; ni < 8; ni++)
                    MMA_BF16(acc[mi][ni], al[mi], (&bhq[ni >> 1][(ni & 1) * 2]));
        }
        __syncthreads();
    }

    float* __restrict__ Cp = p.C + (size_t)slice * (gridDim.y * 128) * DD;
#pragma unroll
    for (int mi = 0; mi < 4; mi++) {
        int gr0 = rowBase + warpM + mi * 16 + quad;
        int gr1 = gr0 + 8;
#pragma unroll
        for (int ni = 0; ni < 8; ni++) {
            int gc = colBase + warpN + ni * 8 + four * 2;
            *(float2*)&Cp[(size_t)gr0 * DD + gc] = make_float2(acc[mi][ni][0], acc[mi][ni][1]);
            *(float2*)&Cp[(size_t)gr1 * DD + gc] = make_float2(acc[mi][ni][2], acc[mi][ni][3]);
        }
    }
}

// ============ single-product fp16 GEMM, 128 threads, k-chunk 32, 3-stage ============
#define STAGE16 20480
#define OFF_B16 10240

struct Gemm16Batch {
    const __half* A[2];
    const __half* B[2];
    const float* bias[2];
    float* C[2];
    __half* C16[2];
    int Mstore;
};

__global__ void __launch_bounds__(128, 2) gemm_f16(const __grid_constant__ Gemm16Batch p)
{
    extern __shared__ char smem[];
    const uint32_t sb = smem_u32(smem);
    const int tid = threadIdx.x;
    const int wid = tid >> 5, lane = tid & 31;
    const int quad = lane >> 2, four = lane & 3;
    const int rowBase = blockIdx.y * 128, colBase = blockIdx.x * 128;
    const int warpM = (wid >> 1) * 64, warpN = (wid & 1) * 64;
    const int z = blockIdx.z;

    const __half* __restrict__ A = p.A[z];
    const __half* __restrict__ B = p.B[z];

    const uint32_t aoff = a_lane_off(lane) + (uint32_t)warpM * PITCH;
    const uint32_t boff = b_lane_off(lane) + (uint32_t)warpN * PITCH + OFF_B16;

    float acc[4][8][4];
#pragma unroll
    for (int mi = 0; mi < 4; mi++)
#pragma unroll
        for (int ni = 0; ni < 8; ni++)
#pragma unroll
            for (int r = 0; r < 4; r++) acc[mi][ni][r] = 0.f;

    auto load_stage = [&](int s, int k0) {
        const uint32_t base = sb + (uint32_t)s * STAGE16;
#pragma unroll
        for (int pp = 0; pp < 4; pp++) {
            int c = tid + pp * 128;
            int row = c >> 2, col = c & 3;
            uint32_t soff = row * PITCH + col * 16;
            cp16(base + soff,            A + (size_t)(rowBase + row) * DD + k0 + col * 8);
            cp16(base + OFF_B16 + soff,  B + (size_t)(colBase + row) * DD + k0 + col * 8);
        }
        asm volatile("cp.async.commit_group;");
    };

    load_stage(0, 0);
    load_stage(1, 32);

    const int NCHUNK = DD / 32;
    int stageIdx = 0;
    for (int cc = 0; cc < NCHUNK; cc++) {
        if (cc + 2 < NCHUNK) {
            int s2 = stageIdx + 2; if (s2 >= 3) s2 -= 3;
            load_stage(s2, (cc + 2) * 32);
            asm volatile("cp.async.wait_group 2;");
        } else if (cc + 1 < NCHUNK) {
            asm volatile("cp.async.wait_group 1;");
        } else {
            asm volatile("cp.async.wait_group 0;");
        }
        __syncthreads();

        const uint32_t stg = sb + (uint32_t)stageIdx * STAGE16;
#pragma unroll
        for (int kk = 0; kk < 2; kk++) {
            const uint32_t kb = kk * 32;
            uint32_t ah[4][4], bq[4][4];
#pragma unroll
            for (int mi = 0; mi < 4; mi++)
                LDSM_X4(ah[mi], stg + aoff + (uint32_t)(mi * 16) * PITCH + kb);
#pragma unroll
            for (int np = 0; np < 4; np++)
                LDSM_X4(bq[np], stg + boff + (uint32_t)(np * 16) * PITCH + kb);
#pragma unroll
            for (int mi = 0; mi < 4; mi++)
#pragma unroll
                for (int ni = 0; ni < 8; ni++)
                    MMA_F16(acc[mi][ni], ah[mi], (&bq[ni >> 1][(ni & 1) * 2]));
        }
        __syncthreads();
        if (++stageIdx == 3) stageIdx = 0;
    }

    const int Mstore = p.Mstore;
    if (p.C16[z]) {
        __half* __restrict__ O = p.C16[z];
#pragma unroll
        for (int mi = 0; mi < 4; mi++) {
            int gr0 = rowBase + warpM + mi * 16 + quad;
            int gr1 = gr0 + 8;
#pragma unroll
            for (int ni = 0; ni < 8; ni++) {
                int gc = colBase + warpN + ni * 8 + four * 2;
                *(__half2*)&O[(size_t)gr0 * DD + gc] =
                    __floats2half2_rn(acc[mi][ni][0], acc[mi][ni][1]);
                *(__half2*)&O[(size_t)gr1 * DD + gc] =
                    __floats2half2_rn(acc[mi][ni][2], acc[mi][ni][3]);
            }
        }
    } else {
        const float* __restrict__ bias = p.bias[z];
        float* __restrict__ C = p.C[z];
#pragma unroll
        for (int mi = 0; mi < 4; mi++) {
            int gr0 = rowBase + warpM + mi * 16 + quad;
            int gr1 = gr0 + 8;
#pragma unroll
            for (int ni = 0; ni < 8; ni++) {
                int gc = colBase + warpN + ni * 8 + four * 2;
                float b0 = bias[gc], b1 = bias[gc + 1];
                if (gr0 < Mstore)
                    *(float2*)&C[(size_t)gr0 * DD + gc] =
                        make_float2(acc[mi][ni][0] + b0, acc[mi][ni][1] + b1);
                if (gr1 < Mstore)
                    *(float2*)&C[(size_t)gr1 * DD + gc] =
                        make_float2(acc[mi][ni][2] + b0, acc[mi][ni][3] + b1);
            }
        }
    }
}

// ============ final reduce ============
__global__ void reduce_final(float* __restrict__ out, const float* __restrict__ bias)
{
    const int r = blockIdx.y;
    const int c = blockIdx.x * 256 + threadIdx.x;
    float a = 0.f;
#pragma unroll
    for (int s = 0; s < 8; s++) a += g_part[(size_t)s * 128 * DD + (size_t)r * DD + c];
    out[(size_t)r * DD + c] = a + bias[c] * g_S[r];
}

// ============ stage-1 window attention, part 1: banded dot partials (k-split) ============
// grid (4, BB), 512 threads. Slice sl covers d in [sl*512, sl*512+512).
__global__ void __launch_bounds__(512) attn1_part(const float* __restrict__ fc)
{
    const int sl = blockIdx.x, b = blockIdx.y;
    const int tid = threadIdx.x;
    const int warp = tid >> 5, lane = tid & 31;
    const int r0 = warp * 4;

    __shared__ float Qc[64][65];
    __shared__ float Kc[64][65];

    float acc[60];
#pragma unroll
    for (int e = 0; e < 60; e++) acc[e] = 0.f;

    for (int ch = sl * 8; ch < sl * 8 + 8; ch++) {
#pragma unroll
        for (int pp = 0; pp < 2; pp++) {
            int f4 = tid + pp * 512;
            int row = f4 >> 4, q = f4 & 15;
            const float4 v = *(const float4*)(g_P + ((size_t)b * NN + row) * DD + ch * 64 + q * 4);
            const float4 u = *(const float4*)(fc  + ((size_t)b * NN + row) * DD + ch * 64 + q * 4);
            Qc[row][q*4+0] = v.x; Qc[row][q*4+1] = v.y; Qc[row][q*4+2] = v.z; Qc[row][q*4+3] = v.w;
            Kc[row][q*4+0] = u.x; Kc[row][q*4+1] = u.y; Kc[row][q*4+2] = u.z; Kc[row][q*4+3] = u.w;
        }
        __syncthreads();
#pragma unroll
        for (int t = 0; t < 2; t++) {
            int dd = lane + t * 32;
            float qv[4];
#pragma unroll
            for (int i = 0; i < 4; i++) qv[i] = Qc[r0 + i][dd];
            float kv[18];
#pragma unroll
            for (int jj = 0; jj < 18; jj++) {
                int cc = r0 - 7 + jj;
                kv[jj] = (cc >= 0 && cc < 64) ? Kc[cc][dd] : 0.f;
            }
#pragma unroll
            for (int i = 0; i < 4; i++)
#pragma unroll
                for (int d5 = 0; d5 < 15; d5++)
                    acc[i * 15 + d5] += qv[i] * kv[i + d5];
        }
        __syncthreads();
    }
#pragma unroll
    for (int e = 0; e < 60; e++) {
#pragma unroll
        for (int off = 16; off; off >>= 1)
            acc[e] += __shfl_xor_sync(0xFFFFFFFFu, acc[e], off);
    }
    if (lane == 0) {
        float* bp = g_band + (((size_t)sl * BB + b) * 64) * 15;
#pragma unroll
        for (int i = 0; i < 4; i++)
#pragma unroll
            for (int d5 = 0; d5 < 15; d5++)
                bp[(size_t)(r0 + i) * 15 + d5] = acc[i * 15 + d5];
    }
}

// ============ stage-1 window attention, part 2: reduce + softmax column sums ============
__global__ void __launch_bounds__(256) attn1_fin()
{
    const int b = blockIdx.x;
    const int tid = threadIdx.x;
    __shared__ float band[64][15];

    for (int idx = tid; idx < 64 * 15; idx += 256) {
        float a = 0.f;
#pragma unroll
        for (int sl = 0; sl < 4; sl++)
            a += g_band[(((size_t)sl * BB + b) * 64) * 15 + idx];
        band[idx / 15][idx % 15] = a;
    }
    __syncthreads();

    if (tid < WW) {
        int w = tid;
        float col[8];
#pragma unroll
        for (int j = 0; j < 8; j++) col[j] = 0.f;
#pragma unroll
        for (int i = 0; i < 8; i++) {
            float s[8], m = -1e30f;
#pragma unroll
            for (int j = 0; j < 8; j++) {
                s[j] = band[w + i][j - i + 7] * SCALE;
                m = fmaxf(m, s[j]);
            }
            float e[8], sum = 0.f;
#pragma unroll
            for (int j = 0; j < 8; j++) { e[j] = __expf(s[j] - m); sum += e[j]; }
            float inv = 1.f / sum;
#pragma unroll
            for (int j = 0; j < 8; j++) col[j] += e[j] * inv;
        }
#pragma unroll
        for (int j = 0; j < 8; j++)
            g_c[((size_t)b * WW + w) * NBW + j] = col[j];
    }
}

// ============ h = downsample + nsa ============
__global__ void coef_kernel(const float* __restrict__ fc, const float* __restrict__ ds_w,
                            const float* __restrict__ ds_b)
{
    const int b = blockIdx.y;
    const int d = blockIdx.x * 128 + threadIdx.x;

    __shared__ float sA[WW * NN];
    __shared__ float sB[WW * NN];
    for (int i = threadIdx.x; i < WW * NN; i += 128) { sA[i] = ds_w[i]; sB[i] = 0.f; }
    __syncthreads();
    for (int i = threadIdx.x; i < WW * NBW; i += 128) {
        int w = i / NBW, j = i % NBW;
        sB[w * NN + w + j] = g_c[((size_t)b * WW + w) * NBW + j];
    }
    __syncthreads();

    const float* fcb = fc + (size_t)b * NN * DD + d;
    const float* vnb = g_Vn + (size_t)b * NN * DD + d;

    float acc[WW];
#pragma unroll
    for (int w = 0; w < WW; w++) acc[w] = 0.f;
    for (int n = 0; n < NN; n++) {
        float fv = fcb[(size_t)n * DD];
        float vv = vnb[(size_t)n * DD];
#pragma unroll
        for (int w = 0; w < WW; w++)
            acc[w] += fv * sA[w * NN + n] + vv * sB[w * NN + n];
    }
    float* hb = g_h + (size_t)b * WW * DD + d;
#pragma unroll
    for (int w = 0; w < WW; w++)
        hb[(size_t)w * DD] = acc[w] + ds_b[w];
}

// ============ LayerNorm -> bf16 hi/lo + fp16 ============
__global__ void ln_split_kernel(const float* __restrict__ g, const float* __restrict__ beta)
{
    const int row = blockIdx.x;
    const int tid = threadIdx.x;
    const float* hr = g_h + (size_t)row * DD;

    float v[8], s = 0.f, s2 = 0.f;
#pragma unroll
    for (int p = 0; p < 8; p++) {
        v[p] = hr[tid + p * 256];
        s += v[p]; s2 += v[p] * v[p];
    }
#pragma unroll
    for (int off = 16; off; off >>= 1) {
        s  += __shfl_xor_sync(0xFFFFFFFFu, s, off);
        s2 += __shfl_xor_sync(0xFFFFFFFFu, s2, off);
    }
    __shared__ float ws[8], ws2[8], smu, sinv;
    const int warp = tid >> 5, lane = tid & 31;
    if (lane == 0) { ws[warp] = s; ws2[warp] = s2; }
    __syncthreads();
    if (warp == 0) {
        float a  = (lane < 8) ? ws[lane]  : 0.f;
        float a2 = (lane < 8) ? ws2[lane] : 0.f;
#pragma unroll
        for (int off = 4; off; off >>= 1) {
            a  += __shfl_xor_sync(0xFFFFFFFFu, a, off);
            a2 += __shfl_xor_sync(0xFFFFFFFFu, a2, off);
        }
        if (lane == 0) {
            float mu = a / (float)DD;
            smu = mu; sinv = rsqrtf(a2 / (float)DD - mu * mu + LNEPS);
        }
    }
    __syncthreads();
    float mu = smu, inv = sinv;
#pragma unroll
    for (int p = 0; p < 8; p++) {
        int d = tid + p * 256;
        float y = (v[p] - mu) * inv * g[d] + beta[d];
        __nv_bfloat16 h = __float2bfloat16(y);
        g_hn_hi[(size_t)row * DD + d] = h;
        g_hn_lo[(size_t)row * DD + d] = __float2bfloat16(y - __bfloat162float(h));
        g_hn16[(size_t)row * DD + d]  = __float2half(y);
    }
}

// ============ stage-2 scores: P2 vs hn16, K-split 64x64 ============
__global__ void dot2_kernel()
{
    const int sl = blockIdx.x, b = blockIdx.y;
    const int tid = threadIdx.x;
    const int ty = tid >> 4, tx = tid & 15;

    __shared__ float Qc[64][33];
    __shared__ float Kc[64][33];

    float acc[4][4];
#pragma unroll
    for (int i = 0; i < 4; i++)
#pragma unroll
        for (int j = 0; j < 4; j++) acc[i][j] = 0.f;

    const size_t rb = (size_t)b * WW;
    for (int ch = 0; ch < 16; ch++) {
        int k0 = sl * 512 + ch * 32;
#pragma unroll
        for (int pq = 0; pq < 2; pq++) {
            int idx = tid + pq * 256;
            int row = idx >> 3, q = idx & 7;
            float4 v = *(const float4*)(g_P2 + (rb + row) * DD + k0 + q * 4);
            Qc[row][q*4+0] = v.x; Qc[row][q*4+1] = v.y; Qc[row][q*4+2] = v.z; Qc[row][q*4+3] = v.w;
        }
        {
            int row = tid >> 2, q = tid & 3;
            const uint4 hv = *(const uint4*)(g_hn16 + (rb + row) * DD + k0 + q * 8);
            const __half* hp = (const __half*)&hv;
#pragma unroll
            for (int e = 0; e < 8; e++)
                Kc[row][q*8+e] = __half2float(hp[e]);
        }
        __syncthreads();
#pragma unroll
        for (int d = 0; d < 32; d++) {
            float ra[4], rv[4];
#pragma unroll
            for (int i = 0; i < 4; i++) ra[i] = Qc[ty * 4 + i][d];
#pragma unroll
            for (int j = 0; j < 4; j++) rv[j] = Kc[tx * 4 + j][d];
#pragma unroll
            for (int i = 0; i < 4; i++)
#pragma unroll
                for (int j = 0; j < 4; j++) acc[i][j] += ra[i] * rv[j];
        }
        __syncthreads();
    }
#pragma unroll
    for (int i = 0; i < 4; i++)
#pragma unroll
        for (int j = 0; j < 4; j++)
            g_dot2[(((size_t)sl * BB + b) * 64 + ty * 4 + i) * 64 + tx * 4 + j] = acc[i][j];
}

// ============ stage-2 softmax column sums ============
__global__ void cw2_kernel()
{
    const int b = blockIdx.x;
    const int tid = threadIdx.x;
    __shared__ float s[WW * 64];
    __shared__ float rmax[WW], rinv[WW], cs[WW];

    for (int idx = tid; idx < WW * 64; idx += 256) {
        int i = idx >> 6, j = idx & 63;
        float v = 0.f;
        if (j < WW) {
#pragma unroll
            for (int sl = 0; sl < 4; sl++)
                v += g_dot2[(((size_t)sl * BB + b) * 64 + i) * 64 + j];
        }
        s[idx] = v * SCALE;
    }
    __syncthreads();
    if (tid < WW) {
        float m = -1e30f;
        for (int j = 0; j < WW; j++) m = fmaxf(m, s[tid * 64 + j]);
        float sum = 0.f;
        for (int j = 0; j < WW; j++) sum += __expf(s[tid * 64 + j] - m);
        rmax[tid] = m; rinv[tid] = 1.f / sum;
    }
    __syncthreads();
    if (tid < WW) {
        float col = 0.f;
        for (int i = 0; i < WW; i++)
            col += __expf(s[i * 64 + tid] - rmax[i]) * rinv[i];
        cs[tid] = col;
        g_cw2[(size_t)b * WW + tid] = col;
    }
    __syncthreads();
    if (tid == 0) {
        float t = 0.f;
        for (int j = 0; j < WW; j++) t += cs[j];
        g_S[b] = t;
    }
}

// ============ hbar -> bf16 hi/lo ============
__global__ void hbar_kernel()
{
    const int b = blockIdx.y;
    const int d = blockIdx.x * 256 + threadIdx.x;

    __shared__ float sc[WW];
    if (threadIdx.x < WW) sc[threadIdx.x] = g_cw2[(size_t)b * WW + threadIdx.x];
    __syncthreads();

    float a = 0.f;
#pragma unroll
    for (int j = 0; j < WW; j++) {
        size_t r = (size_t)(b * WW + j) * DD + d;
        a += sc[j] * (__bfloat162float(g_hn_hi[r]) + __bfloat162float(g_hn_lo[r]));
    }
    __nv_bfloat16 h = __float2bfloat16(a);
    g_hb_hi[(size_t)b * DD + d] = h;
    g_hb_lo[(size_t)b * DD + d] = __float2bfloat16(a - __bfloat162float(h));
}

// ============ launch ============
extern "C" void kernel_launch(void* const* d_in, const int* in_sizes, int n_in,
                              void* d_out, int out_size)
{
    (void)in_sizes; (void)n_in; (void)out_size;

    const float* fc     = (const float*)d_in[0];
    const float* nsa_wq = (const float*)d_in[1];
    const float* nsa_bq = (const float*)d_in[2];
    const float* nsa_wk = (const float*)d_in[3];
    const float* nsa_wv = (const float*)d_in[5];
    const float* nsa_bv = (const float*)d_in[6];
    const float* ds_w   = (const float*)d_in[7];
    const float* ds_b   = (const float*)d_in[8];
    const float* ln_g   = (const float*)d_in[9];
    const float* ln_b   = (const float*)d_in[10];
    const float* sa_wq  = (const float*)d_in[11];
    const float* sa_bq  = (const float*)d_in[12];
    const float* sa_wk  = (const float*)d_in[13];
    const float* sa_wv  = (const float*)d_in[15];
    const float* sa_bv  = (const float*)d_in[16];
    float* out = (float*)d_out;

    float *P, *Vn, *P2, *uu, *part;
    __nv_bfloat16 *wv2h, *wv2l, *hbh, *hbl;
    __half *fc16, *wT16, *wv16, *G16, *hn16;
    cudaGetSymbolAddress((void**)&P,    g_P);
    cudaGetSymbolAddress((void**)&Vn,   g_Vn);
    cudaGetSymbolAddress((void**)&P2,   g_P2);
    cudaGetSymbolAddress((void**)&uu,   g_u);
    cudaGetSymbolAddress((void**)&part, g_part);
    cudaGetSymbolAddress((void**)&fc16, g_fc16);
    cudaGetSymbolAddress((void**)&wT16, g_wT16);
    cudaGetSymbolAddress((void**)&wv16, g_wv16);
    cudaGetSymbolAddress((void**)&wv2h, g_wv2_hi);
    cudaGetSymbolAddress((void**)&wv2l, g_wv2_lo);
    cudaGetSymbolAddress((void**)&G16,  g_G16);
    cudaGetSymbolAddress((void**)&hn16, g_hn16);
    cudaGetSymbolAddress((void**)&hbh,  g_hb_hi);
    cudaGetSymbolAddress((void**)&hbl,  g_hb_lo);

    cudaFuncSetAttribute(gemm_mma_b, cudaFuncAttributeMaxDynamicSharedMemorySize, 2 * STAGE_BYTES);
    cudaFuncSetAttribute(gemm_f16,   cudaFuncAttributeMaxDynamicSharedMemorySize, 3 * STAGE16);

    // --- launches 1-3 ---
    split_all16<<<(BB*NN*DD + 2*(int)NW + 255)/256, 256>>>(fc, nsa_wv, sa_wv);
    {
        SplitTSrc st = { { nsa_wq, nsa_wk, sa_wq, sa_wk } };
        splitT_kernel<<<dim3(32, 32, 4), dim3(32, 8)>>>(st);
    }
    u_part<<<dim3(8, 16, 2), 256>>>(nsa_bq, nsa_wk, sa_bq, sa_wk);
    // --- launch 4 (ncu capture slot): Gram GEMMs ---
    {
        Gemm16Batch p = {};
        p.A[0] = wT16 + 1*NW; p.B[0] = wT16 + 0*NW; p.C16[0] = G16;
        p.A[1] = wT16 + 3*NW; p.B[1] = wT16 + 2*NW; p.C16[1] = G16 + NW;
        p.Mstore = DD;
        gemm_f16<<<dim3(16, 16, 2), 128, 3 * STAGE16>>>(p);
    }
    u_reduce<<<dim3(8, 2), 256>>>();

    // z-batched: P = fc16 @ G16^T + u1;  Vn = fc16 @ wv16^T + bv
    {
        Gemm16Batch p = {};
        p.A[0] = fc16; p.B[0] = G16;  p.bias[0] = uu;     p.C[0] = P;
        p.A[1] = fc16; p.B[1] = wv16; p.bias[1] = nsa_bv; p.C[1] = Vn;
        p.Mstore = BB * NN;
        gemm_f16<<<dim3(16, 32, 2), 128, 3 * STAGE16>>>(p);
    }

    attn1_part<<<dim3(4, BB), 512>>>(fc);
    attn1_fin<<<BB, 256>>>();
    coef_kernel<<<dim3(DD / 128, BB), 128>>>(fc, ds_w, ds_b);
    ln_split_kernel<<<BB * WW, 256>>>(ln_g, ln_b);

    // P2 = hn16 @ G2^T + u2
    {
        Gemm16Batch p = {};
        p.A[0] = hn16; p.B[0] = G16 + NW; p.bias[0] = uu + DD; p.C[0] = P2;
        p.Mstore = MPAD2;
        gemm_f16<<<dim3(16, 29, 1), 128, 3 * STAGE16>>>(p);
    }

    dot2_kernel<<<dim3(4, BB), 256>>>();
    cw2_kernel<<<BB, 256>>>();
    hbar_kernel<<<dim3(DD / 256, BB), 256>>>();

    // final: out = hbar @ Wv2^T + S[b]*bias (3-product bf16, k-split 8, reduce)
    {
        GemmBatch p = {};
        p.Ah = hbh; p.Al = hbl; p.Bh = wv2h; p.Bl = wv2l; p.C = part;
        p.kSplit = 8;
        gemm_mma_b<<<dim3(16, 1, 8), 128, 2 * STAGE_BYTES>>>(p);
    }
    reduce_final<<<dim3(8, BB), 256>>>(out, sa_bv);
}